// round 1
// baseline (speedup 1.0000x reference)
#include <cuda_runtime.h>
#include <math.h>

// Problem constants
#define DD  1024
#define NH  16
#define HDIM 64
#define BB  2
#define NQ  1024
#define NC  4096
#define MQ  (BB*NQ)   // 2048 query rows
#define MC  (BB*NC)   // 8192 context rows

// Scratch (static device globals: allocation-free)
__device__ float g_qn[(size_t)MQ*DD];
__device__ float g_cn[(size_t)MC*DD];
__device__ float g_Qp[(size_t)MQ*DD];
__device__ float g_Kp[(size_t)MC*DD];
__device__ float g_Vp[(size_t)MC*DD];
__device__ float g_AO[(size_t)MQ*DD];

// ---------------------------------------------------------------------------
// LayerNorm: one block per row (D=1024), 256 threads, float4 per thread
// ---------------------------------------------------------------------------
__global__ void __launch_bounds__(256) ln_kernel(
    const float* __restrict__ x, const float* __restrict__ gamma,
    const float* __restrict__ beta, float* __restrict__ y)
{
    int row = blockIdx.x;
    int t = threadIdx.x;
    const float4 v = reinterpret_cast<const float4*>(x + (size_t)row * DD)[t];
    float s  = v.x + v.y + v.z + v.w;
    float ss = v.x*v.x + v.y*v.y + v.z*v.z + v.w*v.w;
    #pragma unroll
    for (int o = 16; o > 0; o >>= 1) {
        s  += __shfl_xor_sync(0xffffffffu, s,  o);
        ss += __shfl_xor_sync(0xffffffffu, ss, o);
    }
    __shared__ float sm1[8], sm2[8];
    int w = t >> 5, l = t & 31;
    if (l == 0) { sm1[w] = s; sm2[w] = ss; }
    __syncthreads();
    if (t < 32) {
        s  = (l < 8) ? sm1[l] : 0.f;
        ss = (l < 8) ? sm2[l] : 0.f;
        #pragma unroll
        for (int o = 4; o > 0; o >>= 1) {
            s  += __shfl_xor_sync(0xffffffffu, s,  o);
            ss += __shfl_xor_sync(0xffffffffu, ss, o);
        }
        if (l == 0) { sm1[0] = s; sm2[0] = ss; }
    }
    __syncthreads();
    const float mu  = sm1[0] * (1.f / DD);
    const float var = sm2[0] * (1.f / DD) - mu * mu;
    const float inv = rsqrtf(var + 1e-5f);
    const float4 g = reinterpret_cast<const float4*>(gamma)[t];
    const float4 b = reinterpret_cast<const float4*>(beta)[t];
    float4 o;
    o.x = (v.x - mu) * inv * g.x + b.x;
    o.y = (v.y - mu) * inv * g.y + b.y;
    o.z = (v.z - mu) * inv * g.z + b.z;
    o.w = (v.w - mu) * inv * g.w + b.w;
    reinterpret_cast<float4*>(y + (size_t)row * DD)[t] = o;
}

// ---------------------------------------------------------------------------
// NT SGEMM: C[M,N] = A[M,K] @ W[N,K]^T + bias[N]  (+ optional residual R)
// BM=BN=128, BK=8, 256 threads, 8x8 register tile per thread.
// ---------------------------------------------------------------------------
#define GBM 128
#define GBN 128
#define GBK 8

__global__ void __launch_bounds__(256) gemm_bias_kernel(
    const float* __restrict__ A, const float* __restrict__ W,
    const float* __restrict__ bias, const float* __restrict__ R,
    float* __restrict__ C, int M, int N, int K)
{
    __shared__ float As[GBK][GBM];
    __shared__ float Bs[GBK][GBN];

    const int t  = threadIdx.x;
    const int m0 = blockIdx.y * GBM;
    const int n0 = blockIdx.x * GBN;

    const int lr = t >> 1;          // 0..127 : row within tile
    const int lk = (t & 1) * 4;     // 0 or 4 : k segment

    const float* Ap = A + (size_t)(m0 + lr) * K + lk;
    const float* Wp = W + (size_t)(n0 + lr) * K + lk;

    const int tr = t >> 4;          // 0..15
    const int tc = t & 15;          // 0..15

    float acc[8][8];
    #pragma unroll
    for (int i = 0; i < 8; i++)
        #pragma unroll
        for (int j = 0; j < 8; j++) acc[i][j] = 0.f;

    for (int k0 = 0; k0 < K; k0 += GBK) {
        const float4 av = *reinterpret_cast<const float4*>(Ap + k0);
        const float4 wv = *reinterpret_cast<const float4*>(Wp + k0);
        As[lk + 0][lr] = av.x; As[lk + 1][lr] = av.y;
        As[lk + 2][lr] = av.z; As[lk + 3][lr] = av.w;
        Bs[lk + 0][lr] = wv.x; Bs[lk + 1][lr] = wv.y;
        Bs[lk + 2][lr] = wv.z; Bs[lk + 3][lr] = wv.w;
        __syncthreads();

        #pragma unroll
        for (int kk = 0; kk < GBK; kk++) {
            float ar[8], br[8];
            *reinterpret_cast<float4*>(ar)     = *reinterpret_cast<const float4*>(&As[kk][tr * 8]);
            *reinterpret_cast<float4*>(ar + 4) = *reinterpret_cast<const float4*>(&As[kk][tr * 8 + 4]);
            *reinterpret_cast<float4*>(br)     = *reinterpret_cast<const float4*>(&Bs[kk][tc * 8]);
            *reinterpret_cast<float4*>(br + 4) = *reinterpret_cast<const float4*>(&Bs[kk][tc * 8 + 4]);
            #pragma unroll
            for (int i = 0; i < 8; i++)
                #pragma unroll
                for (int j = 0; j < 8; j++)
                    acc[i][j] += ar[i] * br[j];
        }
        __syncthreads();
    }

    // Epilogue: bias (+ residual), vectorized stores
    #pragma unroll
    for (int i = 0; i < 8; i++) {
        const size_t gm = (size_t)(m0 + tr * 8 + i);
        float* crow = C + gm * N + n0 + tc * 8;
        const float* rrow = R ? (R + gm * N + n0 + tc * 8) : nullptr;
        #pragma unroll
        for (int j = 0; j < 8; j += 4) {
            float4 o;
            o.x = acc[i][j + 0] + bias[n0 + tc * 8 + j + 0];
            o.y = acc[i][j + 1] + bias[n0 + tc * 8 + j + 1];
            o.z = acc[i][j + 2] + bias[n0 + tc * 8 + j + 2];
            o.w = acc[i][j + 3] + bias[n0 + tc * 8 + j + 3];
            if (rrow) {
                const float4 rv = *reinterpret_cast<const float4*>(rrow + j);
                o.x += rv.x; o.y += rv.y; o.z += rv.z; o.w += rv.w;
            }
            *reinterpret_cast<float4*>(crow + j) = o;
        }
    }
}

// ---------------------------------------------------------------------------
// Flash attention (fp32): block handles 64 queries x one (b,h).
// 128 threads as 16(ty) x 8(tx); each thread owns 4 rows x 8 cols fragments.
// Online softmax with shfl row-reductions over the 8 tx lanes.
// ---------------------------------------------------------------------------
#define ABM 64
#define ABN 64
#define APAD 65
#define SM_TILE (64 * APAD)

__global__ void __launch_bounds__(128) attn_kernel(
    const float* __restrict__ Q, const float* __restrict__ K,
    const float* __restrict__ V, float* __restrict__ O)
{
    extern __shared__ float smem[];
    float* Qs = smem;                 // [64][APAD]
    float* Ks = Qs + SM_TILE;
    float* Vs = Ks + SM_TILE;
    float* Ps = Vs + SM_TILE;

    const int b  = blockIdx.z;
    const int h  = blockIdx.y;
    const int q0 = blockIdx.x * ABM;
    const int t  = threadIdx.x;
    const int ty = t >> 3;            // 0..15
    const int tx = t & 7;             // 0..7

    // Load Q tile (64 x 64)
    const float* Qb = Q + ((size_t)(b * NQ + q0)) * DD + h * HDIM;
    #pragma unroll
    for (int e = t; e < ABM * HDIM; e += 128) {
        int r = e >> 6, c = e & 63;
        Qs[r * APAD + c] = Qb[(size_t)r * DD + c];
    }
    __syncthreads();

    float m_i[4], l_i[4], of[4][8];
    #pragma unroll
    for (int i = 0; i < 4; i++) {
        m_i[i] = -INFINITY; l_i[i] = 0.f;
        #pragma unroll
        for (int j = 0; j < 8; j++) of[i][j] = 0.f;
    }

    const float* Kb = K + ((size_t)(b * NC)) * DD + h * HDIM;
    const float* Vb = V + ((size_t)(b * NC)) * DD + h * HDIM;

    for (int k0 = 0; k0 < NC; k0 += ABN) {
        // Load K,V tiles (coalesced: 128 threads stream 64-float rows)
        #pragma unroll
        for (int e = t; e < ABN * HDIM; e += 128) {
            int r = e >> 6, c = e & 63;
            Ks[r * APAD + c] = Kb[(size_t)(k0 + r) * DD + c];
            Vs[r * APAD + c] = Vb[(size_t)(k0 + r) * DD + c];
        }
        __syncthreads();

        // S = Q K^T fragment (4x8)
        float s[4][8];
        #pragma unroll
        for (int i = 0; i < 4; i++)
            #pragma unroll
            for (int j = 0; j < 8; j++) s[i][j] = 0.f;

        #pragma unroll 4
        for (int k = 0; k < HDIM; k++) {
            float qv[4], kv[8];
            #pragma unroll
            for (int i = 0; i < 4; i++) qv[i] = Qs[(ty * 4 + i) * APAD + k];
            #pragma unroll
            for (int j = 0; j < 8; j++) kv[j] = Ks[(j * 8 + tx) * APAD + k];
            #pragma unroll
            for (int i = 0; i < 4; i++)
                #pragma unroll
                for (int j = 0; j < 8; j++)
                    s[i][j] += qv[i] * kv[j];
        }

        // Online softmax update per row
        #pragma unroll
        for (int i = 0; i < 4; i++) {
            float tm = -INFINITY;
            #pragma unroll
            for (int j = 0; j < 8; j++) {
                s[i][j] *= 0.125f;              // 1/sqrt(64)
                tm = fmaxf(tm, s[i][j]);
            }
            #pragma unroll
            for (int o = 1; o < 8; o <<= 1)
                tm = fmaxf(tm, __shfl_xor_sync(0xffffffffu, tm, o));
            const float mnew = fmaxf(m_i[i], tm);
            const float f = __expf(m_i[i] - mnew);
            float rs = 0.f;
            #pragma unroll
            for (int j = 0; j < 8; j++) {
                const float p = __expf(s[i][j] - mnew);
                Ps[(ty * 4 + i) * APAD + j * 8 + tx] = p;
                rs += p;
            }
            #pragma unroll
            for (int o = 1; o < 8; o <<= 1)
                rs += __shfl_xor_sync(0xffffffffu, rs, o);
            l_i[i] = l_i[i] * f + rs;
            m_i[i] = mnew;
            #pragma unroll
            for (int j = 0; j < 8; j++) of[i][j] *= f;
        }
        __syncthreads();

        // O += P V
        #pragma unroll 4
        for (int kk = 0; kk < ABN; kk++) {
            float pv[4], vv[8];
            #pragma unroll
            for (int i = 0; i < 4; i++) pv[i] = Ps[(ty * 4 + i) * APAD + kk];
            #pragma unroll
            for (int j = 0; j < 8; j++) vv[j] = Vs[kk * APAD + j * 8 + tx];
            #pragma unroll
            for (int i = 0; i < 4; i++)
                #pragma unroll
                for (int j = 0; j < 8; j++)
                    of[i][j] += pv[i] * vv[j];
        }
        __syncthreads();
    }

    // Epilogue
    float* Ob = O + ((size_t)(b * NQ + q0)) * DD + h * HDIM;
    #pragma unroll
    for (int i = 0; i < 4; i++) {
        const float inv = 1.f / l_i[i];
        #pragma unroll
        for (int j = 0; j < 8; j++)
            Ob[(size_t)(ty * 4 + i) * DD + j * 8 + tx] = of[i][j] * inv;
    }
}

// ---------------------------------------------------------------------------
// Launcher
// ---------------------------------------------------------------------------
extern "C" void kernel_launch(void* const* d_in, const int* in_sizes, int n_in,
                              void* d_out, int out_size)
{
    const float* query   = (const float*)d_in[0];
    const float* context = (const float*)d_in[1];
    const float* wq = (const float*)d_in[2];
    const float* bq = (const float*)d_in[3];
    const float* wk = (const float*)d_in[4];
    const float* bk = (const float*)d_in[5];
    const float* wv = (const float*)d_in[6];
    const float* bv = (const float*)d_in[7];
    const float* wo = (const float*)d_in[8];
    const float* bo = (const float*)d_in[9];
    const float* g_q  = (const float*)d_in[10];
    const float* b_q  = (const float*)d_in[11];
    const float* g_kv = (const float*)d_in[12];
    const float* b_kv = (const float*)d_in[13];
    float* out = (float*)d_out;

    void *qn_, *cn_, *qp_, *kp_, *vp_, *ao_;
    cudaGetSymbolAddress(&qn_, g_qn);
    cudaGetSymbolAddress(&cn_, g_cn);
    cudaGetSymbolAddress(&qp_, g_Qp);
    cudaGetSymbolAddress(&kp_, g_Kp);
    cudaGetSymbolAddress(&vp_, g_Vp);
    cudaGetSymbolAddress(&ao_, g_AO);
    float* qn = (float*)qn_; float* cn = (float*)cn_;
    float* Qp = (float*)qp_; float* Kp = (float*)kp_;
    float* Vp = (float*)vp_; float* AO = (float*)ao_;

    const int attn_smem = 4 * SM_TILE * (int)sizeof(float);   // 66560 B
    cudaFuncSetAttribute(attn_kernel, cudaFuncAttributeMaxDynamicSharedMemorySize, attn_smem);

    // 1. LayerNorms
    ln_kernel<<<MQ, 256>>>(query,   g_q,  b_q,  qn);
    ln_kernel<<<MC, 256>>>(context, g_kv, b_kv, cn);

    // 2. Q/K/V projections (NT GEMM + bias)
    dim3 gq(DD / GBN, MQ / GBM);   // (8, 16)
    dim3 gc(DD / GBN, MC / GBM);   // (8, 64)
    gemm_bias_kernel<<<gq, 256>>>(qn, wq, bq, nullptr, Qp, MQ, DD, DD);
    gemm_bias_kernel<<<gc, 256>>>(cn, wk, bk, nullptr, Kp, MC, DD, DD);
    gemm_bias_kernel<<<gc, 256>>>(cn, wv, bv, nullptr, Vp, MC, DD, DD);

    // 3. Flash attention
    dim3 ga(NQ / ABM, NH, BB);     // (16, 16, 2)
    attn_kernel<<<ga, 128, attn_smem>>>(Qp, Kp, Vp, AO);

    // 4. Output projection + bias + residual(qn)
    gemm_bias_kernel<<<gq, 256>>>(AO, wo, bo, qn, out, MQ, DD, DD);
}

// round 2
// speedup vs baseline: 3.0400x; 3.0400x over previous
#include <cuda_runtime.h>
#include <math.h>

// Problem constants
#define DD   1024
#define NH   16
#define HDIM 64
#define BB   2
#define NQ   1024
#define NC   4096
#define MQ   (BB*NQ)   // 2048 query rows
#define MC   (BB*NC)   // 8192 context rows

// Scratch (static device globals: allocation-free)
__device__ float g_qn[(size_t)MQ*DD];
__device__ float g_cn[(size_t)MC*DD];
__device__ float g_Qp[(size_t)MQ*DD];
__device__ float g_Kp[(size_t)MC*DD];
__device__ float g_Vp[(size_t)MC*DD];
__device__ float g_AO[(size_t)MQ*DD];

// ---------------------------------------------------------------------------
// Helpers: tf32 convert + mma.sync
// ---------------------------------------------------------------------------
__device__ __forceinline__ unsigned f2tf(float f) {
    unsigned u;
    asm("cvt.rna.tf32.f32 %0, %1;" : "=r"(u) : "f"(f));
    return u;
}

__device__ __forceinline__ void mma_tf32(float* c, const unsigned* a,
                                         unsigned b0, unsigned b1) {
    asm volatile(
        "mma.sync.aligned.m16n8k8.row.col.f32.tf32.tf32.f32 "
        "{%0,%1,%2,%3}, {%4,%5,%6,%7}, {%8,%9}, {%0,%1,%2,%3};"
        : "+f"(c[0]), "+f"(c[1]), "+f"(c[2]), "+f"(c[3])
        : "r"(a[0]), "r"(a[1]), "r"(a[2]), "r"(a[3]), "r"(b0), "r"(b1));
}

// ---------------------------------------------------------------------------
// LayerNorm: one block per row (D=1024), 256 threads, float4 per thread
// ---------------------------------------------------------------------------
__global__ void __launch_bounds__(256) ln_kernel(
    const float* __restrict__ x, const float* __restrict__ gamma,
    const float* __restrict__ beta, float* __restrict__ y)
{
    int row = blockIdx.x;
    int t = threadIdx.x;
    const float4 v = reinterpret_cast<const float4*>(x + (size_t)row * DD)[t];
    float s  = v.x + v.y + v.z + v.w;
    float ss = v.x*v.x + v.y*v.y + v.z*v.z + v.w*v.w;
    #pragma unroll
    for (int o = 16; o > 0; o >>= 1) {
        s  += __shfl_xor_sync(0xffffffffu, s,  o);
        ss += __shfl_xor_sync(0xffffffffu, ss, o);
    }
    __shared__ float sm1[8], sm2[8];
    int w = t >> 5, l = t & 31;
    if (l == 0) { sm1[w] = s; sm2[w] = ss; }
    __syncthreads();
    if (t < 32) {
        s  = (l < 8) ? sm1[l] : 0.f;
        ss = (l < 8) ? sm2[l] : 0.f;
        #pragma unroll
        for (int o = 4; o > 0; o >>= 1) {
            s  += __shfl_xor_sync(0xffffffffu, s,  o);
            ss += __shfl_xor_sync(0xffffffffu, ss, o);
        }
        if (l == 0) { sm1[0] = s; sm2[0] = ss; }
    }
    __syncthreads();
    const float mu  = sm1[0] * (1.f / DD);
    const float var = sm2[0] * (1.f / DD) - mu * mu;
    const float inv = rsqrtf(var + 1e-5f);
    const float4 g = reinterpret_cast<const float4*>(gamma)[t];
    const float4 b = reinterpret_cast<const float4*>(beta)[t];
    float4 o;
    o.x = (v.x - mu) * inv * g.x + b.x;
    o.y = (v.y - mu) * inv * g.y + b.y;
    o.z = (v.z - mu) * inv * g.z + b.z;
    o.w = (v.w - mu) * inv * g.w + b.w;
    reinterpret_cast<float4*>(y + (size_t)row * DD)[t] = o;
}

// ---------------------------------------------------------------------------
// TF32 tensor-core NT GEMM: C[M,N] = A[M,K] @ W[N,K]^T + bias (+ residual)
// 128x128x16 tile, 256 threads = 8 warps as 4(m) x 2(n), warp tile 32x64.
// Smem tiles [128][20]: stride 20 => conflict-free fragment reads.
// ---------------------------------------------------------------------------
#define GSTR 20

__global__ void __launch_bounds__(256) gemm_tf32_kernel(
    const float* __restrict__ A, const float* __restrict__ W,
    const float* __restrict__ bias, const float* __restrict__ R,
    float* __restrict__ C, int M, int N, int K)
{
    __shared__ unsigned As[128 * GSTR];
    __shared__ unsigned Bs[128 * GSTR];

    const int t    = threadIdx.x;
    const int m0   = blockIdx.y * 128;
    const int n0   = blockIdx.x * 128;
    const int lane = t & 31;
    const int w    = t >> 5;
    const int wm   = w >> 1;        // 0..3
    const int wn   = w & 1;         // 0..1
    const int g    = lane >> 2;     // 0..7
    const int tg   = lane & 3;      // 0..3

    // Global staging map: thread loads rows (t>>2) and (t>>2)+64, k-quad t&3
    const int rowL = t >> 2;        // 0..63
    const int kq   = (t & 3) * 4;

    const float* Ap0 = A + (size_t)(m0 + rowL)      * K + kq;
    const float* Ap1 = A + (size_t)(m0 + rowL + 64) * K + kq;
    const float* Wp0 = W + (size_t)(n0 + rowL)      * K + kq;
    const float* Wp1 = W + (size_t)(n0 + rowL + 64) * K + kq;

    float acc[2][8][4];
    #pragma unroll
    for (int mf = 0; mf < 2; mf++)
        #pragma unroll
        for (int nf = 0; nf < 8; nf++)
            #pragma unroll
            for (int i = 0; i < 4; i++) acc[mf][nf][i] = 0.f;

    // initial prefetch
    float4 ra0 = *reinterpret_cast<const float4*>(Ap0);
    float4 ra1 = *reinterpret_cast<const float4*>(Ap1);
    float4 rb0 = *reinterpret_cast<const float4*>(Wp0);
    float4 rb1 = *reinterpret_cast<const float4*>(Wp1);

    for (int k0 = 0; k0 < K; k0 += 16) {
        // stage current tile (converted to tf32 bits)
        uint4 u;
        u.x = f2tf(ra0.x); u.y = f2tf(ra0.y); u.z = f2tf(ra0.z); u.w = f2tf(ra0.w);
        *reinterpret_cast<uint4*>(&As[rowL * GSTR + kq]) = u;
        u.x = f2tf(ra1.x); u.y = f2tf(ra1.y); u.z = f2tf(ra1.z); u.w = f2tf(ra1.w);
        *reinterpret_cast<uint4*>(&As[(rowL + 64) * GSTR + kq]) = u;
        u.x = f2tf(rb0.x); u.y = f2tf(rb0.y); u.z = f2tf(rb0.z); u.w = f2tf(rb0.w);
        *reinterpret_cast<uint4*>(&Bs[rowL * GSTR + kq]) = u;
        u.x = f2tf(rb1.x); u.y = f2tf(rb1.y); u.z = f2tf(rb1.z); u.w = f2tf(rb1.w);
        *reinterpret_cast<uint4*>(&Bs[(rowL + 64) * GSTR + kq]) = u;
        __syncthreads();

        // prefetch next tile
        if (k0 + 16 < K) {
            ra0 = *reinterpret_cast<const float4*>(Ap0 + k0 + 16);
            ra1 = *reinterpret_cast<const float4*>(Ap1 + k0 + 16);
            rb0 = *reinterpret_cast<const float4*>(Wp0 + k0 + 16);
            rb1 = *reinterpret_cast<const float4*>(Wp1 + k0 + 16);
        }

        // compute 2 k8-steps
        #pragma unroll
        for (int ks = 0; ks < 16; ks += 8) {
            unsigned a[2][4];
            #pragma unroll
            for (int mf = 0; mf < 2; mf++) {
                const int r = wm * 32 + mf * 16 + g;
                a[mf][0] = As[r * GSTR + ks + tg];
                a[mf][1] = As[(r + 8) * GSTR + ks + tg];
                a[mf][2] = As[r * GSTR + ks + tg + 4];
                a[mf][3] = As[(r + 8) * GSTR + ks + tg + 4];
            }
            #pragma unroll
            for (int nf = 0; nf < 8; nf++) {
                const int nr = wn * 64 + nf * 8 + g;
                const unsigned b0 = Bs[nr * GSTR + ks + tg];
                const unsigned b1 = Bs[nr * GSTR + ks + tg + 4];
                mma_tf32(acc[0][nf], a[0], b0, b1);
                mma_tf32(acc[1][nf], a[1], b0, b1);
            }
        }
        __syncthreads();
    }

    // Epilogue: bias (+ residual)
    #pragma unroll
    for (int mf = 0; mf < 2; mf++) {
        #pragma unroll
        for (int nf = 0; nf < 8; nf++) {
            const int col = n0 + wn * 64 + nf * 8 + tg * 2;
            const float bx = bias[col], by = bias[col + 1];
            #pragma unroll
            for (int half = 0; half < 2; half++) {
                const size_t grow = (size_t)(m0 + wm * 32 + mf * 16 + g + half * 8);
                float2 o;
                o.x = acc[mf][nf][half * 2 + 0] + bx;
                o.y = acc[mf][nf][half * 2 + 1] + by;
                if (R) {
                    const float2 rv = *reinterpret_cast<const float2*>(R + grow * N + col);
                    o.x += rv.x; o.y += rv.y;
                }
                *reinterpret_cast<float2*>(C + grow * N + col) = o;
            }
        }
    }
}

// ---------------------------------------------------------------------------
// TF32 tensor-core flash attention.
// Block = 128 q rows x one (b,h); 4 warps, each warp owns 32 q rows (m32).
// K-tile = 64. Smem stride 72 => conflict-free for all fragment patterns.
// ---------------------------------------------------------------------------
#define ASTR 72
#define SZ_Q  (128 * ASTR)
#define SZ_K  (64 * ASTR)
#define SZ_V  (64 * ASTR)
#define SZ_P  (128 * ASTR)

__global__ void __launch_bounds__(128) attn_tf32_kernel(
    const float* __restrict__ Q, const float* __restrict__ K,
    const float* __restrict__ V, float* __restrict__ O)
{
    extern __shared__ unsigned smem[];
    unsigned* Qs = smem;
    unsigned* Ks = Qs + SZ_Q;
    unsigned* Vs = Ks + SZ_K;
    unsigned* Ps = Vs + SZ_V;

    const int b  = blockIdx.z;
    const int h  = blockIdx.y;
    const int q0 = blockIdx.x * 128;
    const int t  = threadIdx.x;
    const int w  = t >> 5;
    const int lane = t & 31;
    const int g  = lane >> 2;    // 0..7
    const int tg = lane & 3;     // 0..3

    // Load Q tile (128 x 64), convert to tf32
    const float* Qb = Q + ((size_t)(b * NQ + q0)) * DD + h * HDIM;
    #pragma unroll
    for (int i = t; i < 128 * 16; i += 128) {
        const int r = i >> 4, c4 = (i & 15) * 4;
        const float4 v = *reinterpret_cast<const float4*>(Qb + (size_t)r * DD + c4);
        uint4 u;
        u.x = f2tf(v.x); u.y = f2tf(v.y); u.z = f2tf(v.z); u.w = f2tf(v.w);
        *reinterpret_cast<uint4*>(&Qs[r * ASTR + c4]) = u;
    }

    float m_i[4], l_i[4], of[2][8][4];
    #pragma unroll
    for (int i = 0; i < 4; i++) { m_i[i] = -INFINITY; l_i[i] = 0.f; }
    #pragma unroll
    for (int mf = 0; mf < 2; mf++)
        #pragma unroll
        for (int nf = 0; nf < 8; nf++)
            #pragma unroll
            for (int i = 0; i < 4; i++) of[mf][nf][i] = 0.f;

    const float* Kb = K + ((size_t)(b * NC)) * DD + h * HDIM;
    const float* Vb = V + ((size_t)(b * NC)) * DD + h * HDIM;

    for (int k0 = 0; k0 < NC; k0 += 64) {
        __syncthreads();  // prior tile fully consumed (also orders Qs on iter 0)
        #pragma unroll
        for (int i = t; i < 64 * 16; i += 128) {
            const int r = i >> 4, c4 = (i & 15) * 4;
            const float4 kv = *reinterpret_cast<const float4*>(Kb + (size_t)(k0 + r) * DD + c4);
            const float4 vv = *reinterpret_cast<const float4*>(Vb + (size_t)(k0 + r) * DD + c4);
            uint4 ku, vu;
            ku.x = f2tf(kv.x); ku.y = f2tf(kv.y); ku.z = f2tf(kv.z); ku.w = f2tf(kv.w);
            vu.x = f2tf(vv.x); vu.y = f2tf(vv.y); vu.z = f2tf(vv.z); vu.w = f2tf(vv.w);
            *reinterpret_cast<uint4*>(&Ks[r * ASTR + c4]) = ku;
            *reinterpret_cast<uint4*>(&Vs[r * ASTR + c4]) = vu;
        }
        __syncthreads();

        // ---- S = Q K^T  (per warp: m32 x n64 over k=64) ----
        float sf[2][8][4];
        #pragma unroll
        for (int mf = 0; mf < 2; mf++)
            #pragma unroll
            for (int nf = 0; nf < 8; nf++)
                #pragma unroll
                for (int i = 0; i < 4; i++) sf[mf][nf][i] = 0.f;

        #pragma unroll
        for (int kk = 0; kk < 8; kk++) {
            unsigned a[2][4];
            #pragma unroll
            for (int mf = 0; mf < 2; mf++) {
                const int r = w * 32 + mf * 16 + g;
                a[mf][0] = Qs[r * ASTR + kk * 8 + tg];
                a[mf][1] = Qs[(r + 8) * ASTR + kk * 8 + tg];
                a[mf][2] = Qs[r * ASTR + kk * 8 + tg + 4];
                a[mf][3] = Qs[(r + 8) * ASTR + kk * 8 + tg + 4];
            }
            #pragma unroll
            for (int nf = 0; nf < 8; nf++) {
                const unsigned b0 = Ks[(nf * 8 + g) * ASTR + kk * 8 + tg];
                const unsigned b1 = Ks[(nf * 8 + g) * ASTR + kk * 8 + tg + 4];
                mma_tf32(sf[0][nf], a[0], b0, b1);
                mma_tf32(sf[1][nf], a[1], b0, b1);
            }
        }

        // ---- online softmax (registers) ----
        #pragma unroll
        for (int mf = 0; mf < 2; mf++) {
            float mx0 = -INFINITY, mx1 = -INFINITY;
            #pragma unroll
            for (int nf = 0; nf < 8; nf++) {
                #pragma unroll
                for (int i = 0; i < 4; i++) sf[mf][nf][i] *= 0.125f;
                mx0 = fmaxf(mx0, fmaxf(sf[mf][nf][0], sf[mf][nf][1]));
                mx1 = fmaxf(mx1, fmaxf(sf[mf][nf][2], sf[mf][nf][3]));
            }
            mx0 = fmaxf(mx0, __shfl_xor_sync(0xffffffffu, mx0, 1));
            mx0 = fmaxf(mx0, __shfl_xor_sync(0xffffffffu, mx0, 2));
            mx1 = fmaxf(mx1, __shfl_xor_sync(0xffffffffu, mx1, 1));
            mx1 = fmaxf(mx1, __shfl_xor_sync(0xffffffffu, mx1, 2));

            const float mn0 = fmaxf(m_i[mf * 2 + 0], mx0);
            const float mn1 = fmaxf(m_i[mf * 2 + 1], mx1);
            const float f0 = __expf(m_i[mf * 2 + 0] - mn0);
            const float f1 = __expf(m_i[mf * 2 + 1] - mn1);

            const int r0 = w * 32 + mf * 16 + g;
            const int r1 = r0 + 8;
            float s0 = 0.f, s1 = 0.f;
            #pragma unroll
            for (int nf = 0; nf < 8; nf++) {
                const float p0 = __expf(sf[mf][nf][0] - mn0);
                const float p1 = __expf(sf[mf][nf][1] - mn0);
                const float p2 = __expf(sf[mf][nf][2] - mn1);
                const float p3 = __expf(sf[mf][nf][3] - mn1);
                s0 += p0 + p1;
                s1 += p2 + p3;
                uint2 u0; u0.x = f2tf(p0); u0.y = f2tf(p1);
                uint2 u1; u1.x = f2tf(p2); u1.y = f2tf(p3);
                *reinterpret_cast<uint2*>(&Ps[r0 * ASTR + nf * 8 + tg * 2]) = u0;
                *reinterpret_cast<uint2*>(&Ps[r1 * ASTR + nf * 8 + tg * 2]) = u1;
            }
            s0 += __shfl_xor_sync(0xffffffffu, s0, 1);
            s0 += __shfl_xor_sync(0xffffffffu, s0, 2);
            s1 += __shfl_xor_sync(0xffffffffu, s1, 1);
            s1 += __shfl_xor_sync(0xffffffffu, s1, 2);

            l_i[mf * 2 + 0] = l_i[mf * 2 + 0] * f0 + s0;
            l_i[mf * 2 + 1] = l_i[mf * 2 + 1] * f1 + s1;
            m_i[mf * 2 + 0] = mn0;
            m_i[mf * 2 + 1] = mn1;

            #pragma unroll
            for (int nf = 0; nf < 8; nf++) {
                of[mf][nf][0] *= f0; of[mf][nf][1] *= f0;
                of[mf][nf][2] *= f1; of[mf][nf][3] *= f1;
            }
        }
        __syncwarp();  // Ps is warp-private; make writes visible

        // ---- O += P V  (per warp: m32 x n64 over k=64) ----
        #pragma unroll
        for (int ks = 0; ks < 8; ks++) {
            unsigned a[2][4];
            #pragma unroll
            for (int mf = 0; mf < 2; mf++) {
                const int r = w * 32 + mf * 16 + g;
                a[mf][0] = Ps[r * ASTR + ks * 8 + tg];
                a[mf][1] = Ps[(r + 8) * ASTR + ks * 8 + tg];
                a[mf][2] = Ps[r * ASTR + ks * 8 + tg + 4];
                a[mf][3] = Ps[(r + 8) * ASTR + ks * 8 + tg + 4];
            }
            #pragma unroll
            for (int nf = 0; nf < 8; nf++) {
                const unsigned b0 = Vs[(ks * 8 + tg) * ASTR + nf * 8 + g];
                const unsigned b1 = Vs[(ks * 8 + tg + 4) * ASTR + nf * 8 + g];
                mma_tf32(of[0][nf], a[0], b0, b1);
                mma_tf32(of[1][nf], a[1], b0, b1);
            }
        }
    }

    // Epilogue: O /= l
    float* Ob = O + ((size_t)(b * NQ + q0)) * DD + h * HDIM;
    #pragma unroll
    for (int mf = 0; mf < 2; mf++) {
        const float inv0 = 1.f / l_i[mf * 2 + 0];
        const float inv1 = 1.f / l_i[mf * 2 + 1];
        #pragma unroll
        for (int nf = 0; nf < 8; nf++) {
            const int col = nf * 8 + tg * 2;
            const int r0 = w * 32 + mf * 16 + g;
            float2 o0, o1;
            o0.x = of[mf][nf][0] * inv0; o0.y = of[mf][nf][1] * inv0;
            o1.x = of[mf][nf][2] * inv1; o1.y = of[mf][nf][3] * inv1;
            *reinterpret_cast<float2*>(Ob + (size_t)r0 * DD + col) = o0;
            *reinterpret_cast<float2*>(Ob + (size_t)(r0 + 8) * DD + col) = o1;
        }
    }
}

// ---------------------------------------------------------------------------
// Launcher
// ---------------------------------------------------------------------------
extern "C" void kernel_launch(void* const* d_in, const int* in_sizes, int n_in,
                              void* d_out, int out_size)
{
    const float* query   = (const float*)d_in[0];
    const float* context = (const float*)d_in[1];
    const float* wq = (const float*)d_in[2];
    const float* bq = (const float*)d_in[3];
    const float* wk = (const float*)d_in[4];
    const float* bk = (const float*)d_in[5];
    const float* wv = (const float*)d_in[6];
    const float* bv = (const float*)d_in[7];
    const float* wo = (const float*)d_in[8];
    const float* bo = (const float*)d_in[9];
    const float* g_q  = (const float*)d_in[10];
    const float* b_q  = (const float*)d_in[11];
    const float* g_kv = (const float*)d_in[12];
    const float* b_kv = (const float*)d_in[13];
    float* out = (float*)d_out;

    void *qn_, *cn_, *qp_, *kp_, *vp_, *ao_;
    cudaGetSymbolAddress(&qn_, g_qn);
    cudaGetSymbolAddress(&cn_, g_cn);
    cudaGetSymbolAddress(&qp_, g_Qp);
    cudaGetSymbolAddress(&kp_, g_Kp);
    cudaGetSymbolAddress(&vp_, g_Vp);
    cudaGetSymbolAddress(&ao_, g_AO);
    float* qn = (float*)qn_; float* cn = (float*)cn_;
    float* Qp = (float*)qp_; float* Kp = (float*)kp_;
    float* Vp = (float*)vp_; float* AO = (float*)ao_;

    const int attn_smem = (SZ_Q + SZ_K + SZ_V + SZ_P) * (int)sizeof(unsigned); // 110592
    static int configured = 0;
    if (!configured) {
        cudaFuncSetAttribute(attn_tf32_kernel,
                             cudaFuncAttributeMaxDynamicSharedMemorySize, attn_smem);
        configured = 1;
    }

    // 1. LayerNorms
    ln_kernel<<<MQ, 256>>>(query,   g_q,  b_q,  qn);
    ln_kernel<<<MC, 256>>>(context, g_kv, b_kv, cn);

    // 2. Q/K/V projections (tf32 tensor-core NT GEMM + bias)
    dim3 gq(DD / 128, MQ / 128);   // (8, 16)
    dim3 gc(DD / 128, MC / 128);   // (8, 64)
    gemm_tf32_kernel<<<gq, 256>>>(qn, wq, bq, nullptr, Qp, MQ, DD, DD);
    gemm_tf32_kernel<<<gc, 256>>>(cn, wk, bk, nullptr, Kp, MC, DD, DD);
    gemm_tf32_kernel<<<gc, 256>>>(cn, wv, bv, nullptr, Vp, MC, DD, DD);

    // 3. Flash attention (tf32 tensor cores)
    dim3 ga(NQ / 128, NH, BB);     // (8, 16, 2)
    attn_tf32_kernel<<<ga, 128, attn_smem>>>(Qp, Kp, Vp, AO);

    // 4. Output projection + bias + residual(qn)
    gemm_tf32_kernel<<<gq, 256>>>(AO, wo, bo, qn, out, MQ, DD, DD);
}

// round 3
// speedup vs baseline: 6.0943x; 2.0047x over previous
#include <cuda_runtime.h>
#include <cuda_bf16.h>
#include <math.h>

// Problem constants
#define DD   1024
#define NH   16
#define HDIM 64
#define BB   2
#define NQ   1024
#define NC   4096
#define MQ   (BB*NQ)   // 2048 query rows
#define MC   (BB*NC)   // 8192 context rows

// Scratch (static device globals: allocation-free)
__device__ float         g_qn [(size_t)MQ*DD];   // fp32 qn (residual)
__device__ __nv_bfloat16 g_qnh[(size_t)MQ*DD];
__device__ __nv_bfloat16 g_cnh[(size_t)MC*DD];
__device__ __nv_bfloat16 g_Qp [(size_t)MQ*DD];
__device__ __nv_bfloat16 g_Kp [(size_t)MC*DD];
__device__ __nv_bfloat16 g_Vp [(size_t)MC*DD];
__device__ __nv_bfloat16 g_AO [(size_t)MQ*DD];
__device__ __nv_bfloat16 g_wqh[(size_t)DD*DD];
__device__ __nv_bfloat16 g_wkh[(size_t)DD*DD];
__device__ __nv_bfloat16 g_wvh[(size_t)DD*DD];
__device__ __nv_bfloat16 g_woh[(size_t)DD*DD];

// ---------------------------------------------------------------------------
// PTX helpers
// ---------------------------------------------------------------------------
__device__ __forceinline__ void mma_bf16(float* c, const unsigned* a,
                                         unsigned b0, unsigned b1) {
    asm volatile(
        "mma.sync.aligned.m16n8k16.row.col.f32.bf16.bf16.f32 "
        "{%0,%1,%2,%3}, {%4,%5,%6,%7}, {%8,%9}, {%0,%1,%2,%3};"
        : "+f"(c[0]), "+f"(c[1]), "+f"(c[2]), "+f"(c[3])
        : "r"(a[0]), "r"(a[1]), "r"(a[2]), "r"(a[3]), "r"(b0), "r"(b1));
}

__device__ __forceinline__ void ldsm_x4(unsigned& r0, unsigned& r1,
                                        unsigned& r2, unsigned& r3, unsigned addr) {
    asm volatile("ldmatrix.sync.aligned.m8n8.x4.shared.b16 {%0,%1,%2,%3}, [%4];"
                 : "=r"(r0), "=r"(r1), "=r"(r2), "=r"(r3) : "r"(addr));
}

__device__ __forceinline__ void ldsm_x4_trans(unsigned& r0, unsigned& r1,
                                              unsigned& r2, unsigned& r3, unsigned addr) {
    asm volatile("ldmatrix.sync.aligned.m8n8.x4.trans.shared.b16 {%0,%1,%2,%3}, [%4];"
                 : "=r"(r0), "=r"(r1), "=r"(r2), "=r"(r3) : "r"(addr));
}

__device__ __forceinline__ void cp_async16(unsigned dst, const void* src) {
    asm volatile("cp.async.cg.shared.global [%0], [%1], 16;" :: "r"(dst), "l"(src));
}
__device__ __forceinline__ void cp_commit() {
    asm volatile("cp.async.commit_group;");
}
__device__ __forceinline__ void cp_wait0() {
    asm volatile("cp.async.wait_group 0;");
}

// ---------------------------------------------------------------------------
// Weight convert fp32 -> bf16
// ---------------------------------------------------------------------------
__global__ void __launch_bounds__(256) cvt_kernel(const float* __restrict__ s,
                                                  __nv_bfloat16* __restrict__ d) {
    const int i = (blockIdx.x * 256 + threadIdx.x) * 4;
    const float4 v = *reinterpret_cast<const float4*>(s + i);
    __nv_bfloat162* o = reinterpret_cast<__nv_bfloat162*>(d + i);
    o[0] = __floats2bfloat162_rn(v.x, v.y);
    o[1] = __floats2bfloat162_rn(v.z, v.w);
}

// ---------------------------------------------------------------------------
// LayerNorm: one block per row (D=1024), 256 threads, float4 per thread.
// Writes bf16 output always; fp32 output optional (residual path).
// ---------------------------------------------------------------------------
__global__ void __launch_bounds__(256) ln_kernel(
    const float* __restrict__ x, const float* __restrict__ gamma,
    const float* __restrict__ beta, float* __restrict__ yf,
    __nv_bfloat16* __restrict__ yh)
{
    int row = blockIdx.x;
    int t = threadIdx.x;
    const float4 v = reinterpret_cast<const float4*>(x + (size_t)row * DD)[t];
    float s  = v.x + v.y + v.z + v.w;
    float ss = v.x*v.x + v.y*v.y + v.z*v.z + v.w*v.w;
    #pragma unroll
    for (int o = 16; o > 0; o >>= 1) {
        s  += __shfl_xor_sync(0xffffffffu, s,  o);
        ss += __shfl_xor_sync(0xffffffffu, ss, o);
    }
    __shared__ float sm1[8], sm2[8];
    int w = t >> 5, l = t & 31;
    if (l == 0) { sm1[w] = s; sm2[w] = ss; }
    __syncthreads();
    if (t < 32) {
        s  = (l < 8) ? sm1[l] : 0.f;
        ss = (l < 8) ? sm2[l] : 0.f;
        #pragma unroll
        for (int o = 4; o > 0; o >>= 1) {
            s  += __shfl_xor_sync(0xffffffffu, s,  o);
            ss += __shfl_xor_sync(0xffffffffu, ss, o);
        }
        if (l == 0) { sm1[0] = s; sm2[0] = ss; }
    }
    __syncthreads();
    const float mu  = sm1[0] * (1.f / DD);
    const float var = sm2[0] * (1.f / DD) - mu * mu;
    const float inv = rsqrtf(var + 1e-5f);
    const float4 g = reinterpret_cast<const float4*>(gamma)[t];
    const float4 b = reinterpret_cast<const float4*>(beta)[t];
    float4 o;
    o.x = (v.x - mu) * inv * g.x + b.x;
    o.y = (v.y - mu) * inv * g.y + b.y;
    o.z = (v.z - mu) * inv * g.z + b.z;
    o.w = (v.w - mu) * inv * g.w + b.w;
    if (yf) reinterpret_cast<float4*>(yf + (size_t)row * DD)[t] = o;
    __nv_bfloat162* oh = reinterpret_cast<__nv_bfloat162*>(yh + (size_t)row * DD + t * 4);
    oh[0] = __floats2bfloat162_rn(o.x, o.y);
    oh[1] = __floats2bfloat162_rn(o.z, o.w);
}

// ---------------------------------------------------------------------------
// BF16 tensor-core NT GEMM: C[M,N] = A[M,K] @ W[N,K]^T + bias (+ residual)
// 128x128x32 tile, 256 threads = 8 warps (4m x 2n), warp tile 32x64.
// Smem rows stride 40 bf16 => conflict-free ldmatrix.
// ---------------------------------------------------------------------------
#define RS 40

__global__ void __launch_bounds__(256) gemm_bf16_kernel(
    const __nv_bfloat16* __restrict__ A, const __nv_bfloat16* __restrict__ W,
    const float* __restrict__ bias, const float* __restrict__ R,
    float* __restrict__ Cf, __nv_bfloat16* __restrict__ Ch,
    int M, int N, int K)
{
    __shared__ __align__(16) __nv_bfloat16 As[128 * RS];
    __shared__ __align__(16) __nv_bfloat16 Bs[128 * RS];

    const int t    = threadIdx.x;
    const int m0   = blockIdx.y * 128;
    const int n0   = blockIdx.x * 128;
    const int lane = t & 31;
    const int w    = t >> 5;
    const int wm   = w >> 1;        // 0..3
    const int wn   = w & 1;         // 0..1
    const int g    = lane >> 2;     // 0..7
    const int tg   = lane & 3;      // 0..3

    const unsigned as_base = (unsigned)__cvta_generic_to_shared(As);
    const unsigned bs_base = (unsigned)__cvta_generic_to_shared(Bs);

    // ldmatrix per-lane components
    const int arow_in  = (lane & 7) + ((lane >> 3) & 1) * 8;
    const int akoff_in = (lane >> 4) * 8;
    const int brow_in  = (lane & 7) + (lane >> 4) * 8;
    const int bkoff_in = ((lane >> 3) & 1) * 8;

    // Global staging: thread loads rows (t>>2) and (t>>2)+64, 16B chunk (t&3)
    const int rowL = t >> 2;        // 0..63
    const int kq   = (t & 3) * 8;   // bf16 offset of 16B chunk

    const __nv_bfloat16* Ap0 = A + (size_t)(m0 + rowL)      * K + kq;
    const __nv_bfloat16* Ap1 = A + (size_t)(m0 + rowL + 64) * K + kq;
    const __nv_bfloat16* Wp0 = W + (size_t)(n0 + rowL)      * K + kq;
    const __nv_bfloat16* Wp1 = W + (size_t)(n0 + rowL + 64) * K + kq;

    float acc[2][8][4];
    #pragma unroll
    for (int mf = 0; mf < 2; mf++)
        #pragma unroll
        for (int nf = 0; nf < 8; nf++)
            #pragma unroll
            for (int i = 0; i < 4; i++) acc[mf][nf][i] = 0.f;

    uint4 ra0 = *reinterpret_cast<const uint4*>(Ap0);
    uint4 ra1 = *reinterpret_cast<const uint4*>(Ap1);
    uint4 rb0 = *reinterpret_cast<const uint4*>(Wp0);
    uint4 rb1 = *reinterpret_cast<const uint4*>(Wp1);

    for (int k0 = 0; k0 < K; k0 += 32) {
        *reinterpret_cast<uint4*>(&As[rowL * RS + kq])        = ra0;
        *reinterpret_cast<uint4*>(&As[(rowL + 64) * RS + kq]) = ra1;
        *reinterpret_cast<uint4*>(&Bs[rowL * RS + kq])        = rb0;
        *reinterpret_cast<uint4*>(&Bs[(rowL + 64) * RS + kq]) = rb1;
        __syncthreads();

        if (k0 + 32 < K) {
            ra0 = *reinterpret_cast<const uint4*>(Ap0 + k0 + 32);
            ra1 = *reinterpret_cast<const uint4*>(Ap1 + k0 + 32);
            rb0 = *reinterpret_cast<const uint4*>(Wp0 + k0 + 32);
            rb1 = *reinterpret_cast<const uint4*>(Wp1 + k0 + 32);
        }

        #pragma unroll
        for (int ks = 0; ks < 2; ks++) {
            unsigned a[2][4];
            #pragma unroll
            for (int mf = 0; mf < 2; mf++) {
                const int r  = wm * 32 + mf * 16 + arow_in;
                const int ko = ks * 16 + akoff_in;
                ldsm_x4(a[mf][0], a[mf][1], a[mf][2], a[mf][3],
                        as_base + (r * RS + ko) * 2);
            }
            unsigned bf[4][4];
            #pragma unroll
            for (int ng = 0; ng < 4; ng++) {
                const int nr = wn * 64 + ng * 16 + brow_in;
                const int ko = ks * 16 + bkoff_in;
                ldsm_x4(bf[ng][0], bf[ng][1], bf[ng][2], bf[ng][3],
                        bs_base + (nr * RS + ko) * 2);
            }
            #pragma unroll
            for (int ng = 0; ng < 4; ng++) {
                mma_bf16(acc[0][2*ng+0], a[0], bf[ng][0], bf[ng][1]);
                mma_bf16(acc[1][2*ng+0], a[1], bf[ng][0], bf[ng][1]);
                mma_bf16(acc[0][2*ng+1], a[0], bf[ng][2], bf[ng][3]);
                mma_bf16(acc[1][2*ng+1], a[1], bf[ng][2], bf[ng][3]);
            }
        }
        __syncthreads();
    }

    // Epilogue
    #pragma unroll
    for (int mf = 0; mf < 2; mf++) {
        #pragma unroll
        for (int nf = 0; nf < 8; nf++) {
            const int col = n0 + wn * 64 + nf * 8 + tg * 2;
            const float bx = bias[col], by = bias[col + 1];
            #pragma unroll
            for (int half = 0; half < 2; half++) {
                const size_t grow = (size_t)(m0 + wm * 32 + mf * 16 + g + half * 8);
                float ox = acc[mf][nf][half * 2 + 0] + bx;
                float oy = acc[mf][nf][half * 2 + 1] + by;
                if (Ch) {
                    *reinterpret_cast<__nv_bfloat162*>(Ch + grow * N + col) =
                        __floats2bfloat162_rn(ox, oy);
                } else {
                    if (R) {
                        const float2 rv = *reinterpret_cast<const float2*>(R + grow * N + col);
                        ox += rv.x; oy += rv.y;
                    }
                    float2 o; o.x = ox; o.y = oy;
                    *reinterpret_cast<float2*>(Cf + grow * N + col) = o;
                }
            }
        }
    }
}

// ---------------------------------------------------------------------------
// BF16 tensor-core flash attention.
// Block = 128 q rows x one (b,h); 4 warps, warp tile m32 x n64.
// K/V tiles (64 x 64) double-buffered via cp.async.
// Smem row stride 72 bf16 => conflict-free ldmatrix (incl. trans).
// ---------------------------------------------------------------------------
#define QSTR 72
#define OFF_Q 0
#define OFF_K (128 * QSTR)
#define OFF_V (OFF_K + 2 * 64 * QSTR)
#define OFF_P (OFF_V + 2 * 64 * QSTR)
#define SM_ELEMS (OFF_P + 128 * QSTR)
#define KVBUF (64 * QSTR)

__global__ void __launch_bounds__(128) attn_bf16_kernel(
    const __nv_bfloat16* __restrict__ Q, const __nv_bfloat16* __restrict__ K,
    const __nv_bfloat16* __restrict__ V, __nv_bfloat16* __restrict__ O)
{
    extern __shared__ __align__(16) __nv_bfloat16 smem[];
    const unsigned sm_base = (unsigned)__cvta_generic_to_shared(smem);

    const int b  = blockIdx.z;
    const int h  = blockIdx.y;
    const int q0 = blockIdx.x * 128;
    const int t  = threadIdx.x;
    const int w  = t >> 5;
    const int lane = t & 31;
    const int g  = lane >> 2;
    const int tg = lane & 3;

    const int arow_in  = (lane & 7) + ((lane >> 3) & 1) * 8;
    const int akoff_in = (lane >> 4) * 8;
    const int brow_in  = (lane & 7) + (lane >> 4) * 8;
    const int bkoff_in = ((lane >> 3) & 1) * 8;

    const __nv_bfloat16* Qb = Q + ((size_t)(b * NQ + q0)) * DD + h * HDIM;
    const __nv_bfloat16* Kb = K + ((size_t)(b * NC)) * DD + h * HDIM;
    const __nv_bfloat16* Vb = V + ((size_t)(b * NC)) * DD + h * HDIM;

    // Prologue: async-load Q (128x64) and K/V tile 0 (64x64 each)
    {
        // Q: thread t -> row t, 8 chunks of 16B
        #pragma unroll
        for (int c = 0; c < 8; c++)
            cp_async16(sm_base + (OFF_Q + t * QSTR + c * 8) * 2,
                       Qb + (size_t)t * DD + c * 8);
        const int r = t >> 1;
        const int cb = (t & 1) * 4;
        #pragma unroll
        for (int c = 0; c < 4; c++) {
            cp_async16(sm_base + (OFF_K + r * QSTR + (cb + c) * 8) * 2,
                       Kb + (size_t)r * DD + (cb + c) * 8);
            cp_async16(sm_base + (OFF_V + r * QSTR + (cb + c) * 8) * 2,
                       Vb + (size_t)r * DD + (cb + c) * 8);
        }
        cp_commit();
    }

    float m_i[4], l_i[4], of[2][8][4];
    #pragma unroll
    for (int i = 0; i < 4; i++) { m_i[i] = -INFINITY; l_i[i] = 0.f; }
    #pragma unroll
    for (int mf = 0; mf < 2; mf++)
        #pragma unroll
        for (int nf = 0; nf < 8; nf++)
            #pragma unroll
            for (int i = 0; i < 4; i++) of[mf][nf][i] = 0.f;

    const int NT = NC / 64;
    for (int it = 0; it < NT; it++) {
        const int cur = it & 1;
        cp_wait0();
        __syncthreads();

        // Prefetch next K/V tile into the other buffer
        if (it + 1 < NT) {
            const int nxt = cur ^ 1;
            const int r = t >> 1;
            const int cb = (t & 1) * 4;
            const size_t grow = (size_t)((it + 1) * 64 + r) * DD;
            #pragma unroll
            for (int c = 0; c < 4; c++) {
                cp_async16(sm_base + (OFF_K + nxt * KVBUF + r * QSTR + (cb + c) * 8) * 2,
                           Kb + grow + (cb + c) * 8);
                cp_async16(sm_base + (OFF_V + nxt * KVBUF + r * QSTR + (cb + c) * 8) * 2,
                           Vb + grow + (cb + c) * 8);
            }
            cp_commit();
        }

        const int kbase = OFF_K + cur * KVBUF;
        const int vbase = OFF_V + cur * KVBUF;

        // ---- S = Q K^T : m32 x n64, k=64 (4 k16 steps) ----
        float sf[2][8][4];
        #pragma unroll
        for (int mf = 0; mf < 2; mf++)
            #pragma unroll
            for (int nf = 0; nf < 8; nf++)
                #pragma unroll
                for (int i = 0; i < 4; i++) sf[mf][nf][i] = 0.f;

        #pragma unroll
        for (int ks = 0; ks < 4; ks++) {
            unsigned a[2][4];
            #pragma unroll
            for (int mf = 0; mf < 2; mf++) {
                const int r  = w * 32 + mf * 16 + arow_in;
                const int ko = ks * 16 + akoff_in;
                ldsm_x4(a[mf][0], a[mf][1], a[mf][2], a[mf][3],
                        sm_base + (OFF_Q + r * QSTR + ko) * 2);
            }
            unsigned bf[4][4];
            #pragma unroll
            for (int ng = 0; ng < 4; ng++) {
                const int nr = ng * 16 + brow_in;
                const int ko = ks * 16 + bkoff_in;
                ldsm_x4(bf[ng][0], bf[ng][1], bf[ng][2], bf[ng][3],
                        sm_base + (kbase + nr * QSTR + ko) * 2);
            }
            #pragma unroll
            for (int ng = 0; ng < 4; ng++) {
                mma_bf16(sf[0][2*ng+0], a[0], bf[ng][0], bf[ng][1]);
                mma_bf16(sf[1][2*ng+0], a[1], bf[ng][0], bf[ng][1]);
                mma_bf16(sf[0][2*ng+1], a[0], bf[ng][2], bf[ng][3]);
                mma_bf16(sf[1][2*ng+1], a[1], bf[ng][2], bf[ng][3]);
            }
        }

        // ---- online softmax ----
        #pragma unroll
        for (int mf = 0; mf < 2; mf++) {
            float mx0 = -INFINITY, mx1 = -INFINITY;
            #pragma unroll
            for (int nf = 0; nf < 8; nf++) {
                #pragma unroll
                for (int i = 0; i < 4; i++) sf[mf][nf][i] *= 0.125f;
                mx0 = fmaxf(mx0, fmaxf(sf[mf][nf][0], sf[mf][nf][1]));
                mx1 = fmaxf(mx1, fmaxf(sf[mf][nf][2], sf[mf][nf][3]));
            }
            mx0 = fmaxf(mx0, __shfl_xor_sync(0xffffffffu, mx0, 1));
            mx0 = fmaxf(mx0, __shfl_xor_sync(0xffffffffu, mx0, 2));
            mx1 = fmaxf(mx1, __shfl_xor_sync(0xffffffffu, mx1, 1));
            mx1 = fmaxf(mx1, __shfl_xor_sync(0xffffffffu, mx1, 2));

            const float mn0 = fmaxf(m_i[mf * 2 + 0], mx0);
            const float mn1 = fmaxf(m_i[mf * 2 + 1], mx1);
            const float f0 = __expf(m_i[mf * 2 + 0] - mn0);
            const float f1 = __expf(m_i[mf * 2 + 1] - mn1);

            const int r0 = w * 32 + mf * 16 + g;
            const int r1 = r0 + 8;
            float s0 = 0.f, s1 = 0.f;
            #pragma unroll
            for (int nf = 0; nf < 8; nf++) {
                const float p0 = __expf(sf[mf][nf][0] - mn0);
                const float p1 = __expf(sf[mf][nf][1] - mn0);
                const float p2 = __expf(sf[mf][nf][2] - mn1);
                const float p3 = __expf(sf[mf][nf][3] - mn1);
                s0 += p0 + p1;
                s1 += p2 + p3;
                *reinterpret_cast<__nv_bfloat162*>(&smem[OFF_P + r0 * QSTR + nf * 8 + tg * 2]) =
                    __floats2bfloat162_rn(p0, p1);
                *reinterpret_cast<__nv_bfloat162*>(&smem[OFF_P + r1 * QSTR + nf * 8 + tg * 2]) =
                    __floats2bfloat162_rn(p2, p3);
            }
            s0 += __shfl_xor_sync(0xffffffffu, s0, 1);
            s0 += __shfl_xor_sync(0xffffffffu, s0, 2);
            s1 += __shfl_xor_sync(0xffffffffu, s1, 1);
            s1 += __shfl_xor_sync(0xffffffffu, s1, 2);

            l_i[mf * 2 + 0] = l_i[mf * 2 + 0] * f0 + s0;
            l_i[mf * 2 + 1] = l_i[mf * 2 + 1] * f1 + s1;
            m_i[mf * 2 + 0] = mn0;
            m_i[mf * 2 + 1] = mn1;

            #pragma unroll
            for (int nf = 0; nf < 8; nf++) {
                of[mf][nf][0] *= f0; of[mf][nf][1] *= f0;
                of[mf][nf][2] *= f1; of[mf][nf][3] *= f1;
            }
        }
        __syncwarp();

        // ---- O += P V : m32 x n64, k=64 (4 k16 steps) ----
        #pragma unroll
        for (int ks = 0; ks < 4; ks++) {
            unsigned a[2][4];
            #pragma unroll
            for (int mf = 0; mf < 2; mf++) {
                const int r  = w * 32 + mf * 16 + arow_in;
                const int ko = ks * 16 + akoff_in;
                ldsm_x4(a[mf][0], a[mf][1], a[mf][2], a[mf][3],
                        sm_base + (OFF_P + r * QSTR + ko) * 2);
            }
            unsigned bf[4][4];
            #pragma unroll
            for (int ng = 0; ng < 4; ng++) {
                // trans: rows = ctx (k), cols = head-dim (n)
                const int kr = ks * 16 + arow_in;
                const int nc = ng * 16 + akoff_in;
                ldsm_x4_trans(bf[ng][0], bf[ng][1], bf[ng][2], bf[ng][3],
                              sm_base + (vbase + kr * QSTR + nc) * 2);
            }
            #pragma unroll
            for (int ng = 0; ng < 4; ng++) {
                mma_bf16(of[0][2*ng+0], a[0], bf[ng][0], bf[ng][1]);
                mma_bf16(of[1][2*ng+0], a[1], bf[ng][0], bf[ng][1]);
                mma_bf16(of[0][2*ng+1], a[0], bf[ng][2], bf[ng][3]);
                mma_bf16(of[1][2*ng+1], a[1], bf[ng][2], bf[ng][3]);
            }
        }
    }

    // Epilogue: O /= l, write bf16
    __nv_bfloat16* Ob = O + ((size_t)(b * NQ + q0)) * DD + h * HDIM;
    #pragma unroll
    for (int mf = 0; mf < 2; mf++) {
        const float inv0 = 1.f / l_i[mf * 2 + 0];
        const float inv1 = 1.f / l_i[mf * 2 + 1];
        #pragma unroll
        for (int nf = 0; nf < 8; nf++) {
            const int col = nf * 8 + tg * 2;
            const int r0 = w * 32 + mf * 16 + g;
            *reinterpret_cast<__nv_bfloat162*>(Ob + (size_t)r0 * DD + col) =
                __floats2bfloat162_rn(of[mf][nf][0] * inv0, of[mf][nf][1] * inv0);
            *reinterpret_cast<__nv_bfloat162*>(Ob + (size_t)(r0 + 8) * DD + col) =
                __floats2bfloat162_rn(of[mf][nf][2] * inv1, of[mf][nf][3] * inv1);
        }
    }
}

// ---------------------------------------------------------------------------
// Launcher
// ---------------------------------------------------------------------------
extern "C" void kernel_launch(void* const* d_in, const int* in_sizes, int n_in,
                              void* d_out, int out_size)
{
    const float* query   = (const float*)d_in[0];
    const float* context = (const float*)d_in[1];
    const float* wq = (const float*)d_in[2];
    const float* bq = (const float*)d_in[3];
    const float* wk = (const float*)d_in[4];
    const float* bk = (const float*)d_in[5];
    const float* wv = (const float*)d_in[6];
    const float* bv = (const float*)d_in[7];
    const float* wo = (const float*)d_in[8];
    const float* bo = (const float*)d_in[9];
    const float* g_q  = (const float*)d_in[10];
    const float* b_q  = (const float*)d_in[11];
    const float* g_kv = (const float*)d_in[12];
    const float* b_kv = (const float*)d_in[13];
    float* out = (float*)d_out;

    void *qn_, *qnh_, *cnh_, *qp_, *kp_, *vp_, *ao_, *wqh_, *wkh_, *wvh_, *woh_;
    cudaGetSymbolAddress(&qn_,  g_qn);
    cudaGetSymbolAddress(&qnh_, g_qnh);
    cudaGetSymbolAddress(&cnh_, g_cnh);
    cudaGetSymbolAddress(&qp_,  g_Qp);
    cudaGetSymbolAddress(&kp_,  g_Kp);
    cudaGetSymbolAddress(&vp_,  g_Vp);
    cudaGetSymbolAddress(&ao_,  g_AO);
    cudaGetSymbolAddress(&wqh_, g_wqh);
    cudaGetSymbolAddress(&wkh_, g_wkh);
    cudaGetSymbolAddress(&wvh_, g_wvh);
    cudaGetSymbolAddress(&woh_, g_woh);
    float* qn = (float*)qn_;
    __nv_bfloat16* qnh = (__nv_bfloat16*)qnh_;
    __nv_bfloat16* cnh = (__nv_bfloat16*)cnh_;
    __nv_bfloat16* Qp  = (__nv_bfloat16*)qp_;
    __nv_bfloat16* Kp  = (__nv_bfloat16*)kp_;
    __nv_bfloat16* Vp  = (__nv_bfloat16*)vp_;
    __nv_bfloat16* AO  = (__nv_bfloat16*)ao_;
    __nv_bfloat16* wqh = (__nv_bfloat16*)wqh_;
    __nv_bfloat16* wkh = (__nv_bfloat16*)wkh_;
    __nv_bfloat16* wvh = (__nv_bfloat16*)wvh_;
    __nv_bfloat16* woh = (__nv_bfloat16*)woh_;

    const int attn_smem = SM_ELEMS * 2;   // 73728 bytes
    static int configured = 0;
    if (!configured) {
        cudaFuncSetAttribute(attn_bf16_kernel,
                             cudaFuncAttributeMaxDynamicSharedMemorySize, attn_smem);
        configured = 1;
    }

    // 0. Weight conversion fp32 -> bf16
    const int cvt_grid = (DD * DD / 4) / 256;
    cvt_kernel<<<cvt_grid, 256>>>(wq, wqh);
    cvt_kernel<<<cvt_grid, 256>>>(wk, wkh);
    cvt_kernel<<<cvt_grid, 256>>>(wv, wvh);
    cvt_kernel<<<cvt_grid, 256>>>(wo, woh);

    // 1. LayerNorms (fp32 qn kept for residual; bf16 copies feed GEMMs)
    ln_kernel<<<MQ, 256>>>(query,   g_q,  b_q,  qn,      qnh);
    ln_kernel<<<MC, 256>>>(context, g_kv, b_kv, nullptr, cnh);

    // 2. Q/K/V projections (bf16 tensor-core NT GEMM + bias, bf16 out)
    dim3 gq(DD / 128, MQ / 128);   // (8, 16)
    dim3 gc(DD / 128, MC / 128);   // (8, 64)
    gemm_bf16_kernel<<<gq, 256>>>(qnh, wqh, bq, nullptr, nullptr, Qp, MQ, DD, DD);
    gemm_bf16_kernel<<<gc, 256>>>(cnh, wkh, bk, nullptr, nullptr, Kp, MC, DD, DD);
    gemm_bf16_kernel<<<gc, 256>>>(cnh, wvh, bv, nullptr, nullptr, Vp, MC, DD, DD);

    // 3. Flash attention (bf16 tensor cores, cp.async double-buffered K/V)
    dim3 ga(NQ / 128, NH, BB);     // (8, 16, 2)
    attn_bf16_kernel<<<ga, 128, attn_smem>>>(Qp, Kp, Vp, AO);

    // 4. Output projection + bias + residual(qn), fp32 out
    gemm_bf16_kernel<<<gq, 256>>>(AO, woh, bo, qn, out, nullptr, MQ, DD, DD);
}

// round 4
// speedup vs baseline: 6.3645x; 1.0443x over previous
#include <cuda_runtime.h>
#include <cuda_bf16.h>
#include <math.h>

// Problem constants
#define DD   1024
#define NH   16
#define HDIM 64
#define BB   2
#define NQ   1024
#define NC   4096
#define MQ   (BB*NQ)   // 2048 query rows
#define MC   (BB*NC)   // 8192 context rows

// Scratch (static device globals: allocation-free)
__device__ float         g_qn  [(size_t)MQ*DD];   // fp32 qn (residual)
__device__ __nv_bfloat16 g_qnh [(size_t)MQ*DD];
__device__ __nv_bfloat16 g_cnh [(size_t)MC*DD];
__device__ __nv_bfloat16 g_Qp  [(size_t)MQ*DD];
__device__ __nv_bfloat16 g_Kp  [(size_t)MC*DD];
__device__ __nv_bfloat16 g_Vp  [(size_t)MC*DD];
__device__ __nv_bfloat16 g_AO  [(size_t)MQ*DD];
__device__ __nv_bfloat16 g_wqh [(size_t)DD*DD];
__device__ __nv_bfloat16 g_wkvh[(size_t)2*DD*DD]; // concat [wk; wv]
__device__ __nv_bfloat16 g_woh [(size_t)DD*DD];

// ---------------------------------------------------------------------------
// PTX helpers
// ---------------------------------------------------------------------------
__device__ __forceinline__ void mma_bf16(float* c, const unsigned* a,
                                         unsigned b0, unsigned b1) {
    asm volatile(
        "mma.sync.aligned.m16n8k16.row.col.f32.bf16.bf16.f32 "
        "{%0,%1,%2,%3}, {%4,%5,%6,%7}, {%8,%9}, {%0,%1,%2,%3};"
        : "+f"(c[0]), "+f"(c[1]), "+f"(c[2]), "+f"(c[3])
        : "r"(a[0]), "r"(a[1]), "r"(a[2]), "r"(a[3]), "r"(b0), "r"(b1));
}

__device__ __forceinline__ void ldsm_x4(unsigned& r0, unsigned& r1,
                                        unsigned& r2, unsigned& r3, unsigned addr) {
    asm volatile("ldmatrix.sync.aligned.m8n8.x4.shared.b16 {%0,%1,%2,%3}, [%4];"
                 : "=r"(r0), "=r"(r1), "=r"(r2), "=r"(r3) : "r"(addr));
}

__device__ __forceinline__ void ldsm_x4_trans(unsigned& r0, unsigned& r1,
                                              unsigned& r2, unsigned& r3, unsigned addr) {
    asm volatile("ldmatrix.sync.aligned.m8n8.x4.trans.shared.b16 {%0,%1,%2,%3}, [%4];"
                 : "=r"(r0), "=r"(r1), "=r"(r2), "=r"(r3) : "r"(addr));
}

__device__ __forceinline__ void cp_async16(unsigned dst, const void* src) {
    asm volatile("cp.async.cg.shared.global [%0], [%1], 16;" :: "r"(dst), "l"(src));
}
__device__ __forceinline__ void cp_commit() {
    asm volatile("cp.async.commit_group;");
}
template <int N>
__device__ __forceinline__ void cp_wait() {
    asm volatile("cp.async.wait_group %0;" :: "n"(N));
}

// ---------------------------------------------------------------------------
// Fused weight convert fp32 -> bf16 : wq -> wqh, wk/wv -> wkvh, wo -> woh
// blockIdx.y selects the matrix.
// ---------------------------------------------------------------------------
__global__ void __launch_bounds__(256) cvt4_kernel(
    const float* __restrict__ wq, const float* __restrict__ wk,
    const float* __restrict__ wv, const float* __restrict__ wo,
    __nv_bfloat16* __restrict__ wqh, __nv_bfloat16* __restrict__ wkvh,
    __nv_bfloat16* __restrict__ woh)
{
    const int i = (blockIdx.x * 256 + threadIdx.x) * 4;
    const int m = blockIdx.y;
    const float* s;
    __nv_bfloat16* d;
    if      (m == 0) { s = wq; d = wqh; }
    else if (m == 1) { s = wk; d = wkvh; }
    else if (m == 2) { s = wv; d = wkvh + (size_t)DD * DD; }
    else             { s = wo; d = woh; }
    const float4 v = *reinterpret_cast<const float4*>(s + i);
    __nv_bfloat162* o = reinterpret_cast<__nv_bfloat162*>(d + i);
    o[0] = __floats2bfloat162_rn(v.x, v.y);
    o[1] = __floats2bfloat162_rn(v.z, v.w);
}

// ---------------------------------------------------------------------------
// LayerNorm: one block per row (D=1024), 256 threads, float4 per thread.
// ---------------------------------------------------------------------------
__global__ void __launch_bounds__(256) ln_kernel(
    const float* __restrict__ x, const float* __restrict__ gamma,
    const float* __restrict__ beta, float* __restrict__ yf,
    __nv_bfloat16* __restrict__ yh)
{
    int row = blockIdx.x;
    int t = threadIdx.x;
    const float4 v = reinterpret_cast<const float4*>(x + (size_t)row * DD)[t];
    float s  = v.x + v.y + v.z + v.w;
    float ss = v.x*v.x + v.y*v.y + v.z*v.z + v.w*v.w;
    #pragma unroll
    for (int o = 16; o > 0; o >>= 1) {
        s  += __shfl_xor_sync(0xffffffffu, s,  o);
        ss += __shfl_xor_sync(0xffffffffu, ss, o);
    }
    __shared__ float sm1[8], sm2[8];
    int w = t >> 5, l = t & 31;
    if (l == 0) { sm1[w] = s; sm2[w] = ss; }
    __syncthreads();
    if (t < 32) {
        s  = (l < 8) ? sm1[l] : 0.f;
        ss = (l < 8) ? sm2[l] : 0.f;
        #pragma unroll
        for (int o = 4; o > 0; o >>= 1) {
            s  += __shfl_xor_sync(0xffffffffu, s,  o);
            ss += __shfl_xor_sync(0xffffffffu, ss, o);
        }
        if (l == 0) { sm1[0] = s; sm2[0] = ss; }
    }
    __syncthreads();
    const float mu  = sm1[0] * (1.f / DD);
    const float var = sm2[0] * (1.f / DD) - mu * mu;
    const float inv = rsqrtf(var + 1e-5f);
    const float4 g = reinterpret_cast<const float4*>(gamma)[t];
    const float4 b = reinterpret_cast<const float4*>(beta)[t];
    float4 o;
    o.x = (v.x - mu) * inv * g.x + b.x;
    o.y = (v.y - mu) * inv * g.y + b.y;
    o.z = (v.z - mu) * inv * g.z + b.z;
    o.w = (v.w - mu) * inv * g.w + b.w;
    if (yf) reinterpret_cast<float4*>(yf + (size_t)row * DD)[t] = o;
    __nv_bfloat162* oh = reinterpret_cast<__nv_bfloat162*>(yh + (size_t)row * DD + t * 4);
    oh[0] = __floats2bfloat162_rn(o.x, o.y);
    oh[1] = __floats2bfloat162_rn(o.z, o.w);
}

// ---------------------------------------------------------------------------
// BF16 tensor-core NT GEMM, cp.async 3-stage pipeline.
// C[M, Nw] = A[M,K] @ W[Nw,K]^T ; output columns < 1024 -> (bias, Ch/Cf),
// columns >= 1024 -> (bias2, Ch2). Output row stride is always DD.
// 128x128x32 CTA tile, 256 threads = 8 warps (4m x 2n), warp tile 32x64.
// Smem rows stride 40 bf16 => conflict-free ldmatrix.
// ---------------------------------------------------------------------------
#define RS 40
#define GTILE (128 * RS)

__global__ void __launch_bounds__(256) gemm_bf16_kernel(
    const __nv_bfloat16* __restrict__ A, const __nv_bfloat16* __restrict__ W,
    const float* __restrict__ bias, const float* __restrict__ bias2,
    const float* __restrict__ R,
    float* __restrict__ Cf,
    __nv_bfloat16* __restrict__ Ch, __nv_bfloat16* __restrict__ Ch2,
    int M, int K)
{
    extern __shared__ __align__(16) __nv_bfloat16 gsm[];
    __nv_bfloat16* As = gsm;                 // [3][128*RS]
    __nv_bfloat16* Bs = gsm + 3 * GTILE;     // [3][128*RS]

    const int t    = threadIdx.x;
    const int m0   = blockIdx.y * 128;
    const int n0   = blockIdx.x * 128;
    const int lane = t & 31;
    const int w    = t >> 5;
    const int wm   = w >> 1;
    const int wn   = w & 1;
    const int g    = lane >> 2;
    const int tg   = lane & 3;

    const unsigned as_base = (unsigned)__cvta_generic_to_shared(As);
    const unsigned bs_base = (unsigned)__cvta_generic_to_shared(Bs);

    const int arow_in  = (lane & 7) + ((lane >> 3) & 1) * 8;
    const int akoff_in = (lane >> 4) * 8;
    const int brow_in  = (lane & 7) + (lane >> 4) * 8;
    const int bkoff_in = ((lane >> 3) & 1) * 8;

    // cp.async staging: thread t covers row t>>1, bf16 cols [(t&1)*16, +16)
    const int srow = t >> 1;          // 0..127
    const int sc   = (t & 1) * 16;    // 0 or 16

    const __nv_bfloat16* Ap = A + (size_t)(m0 + srow) * K + sc;
    const __nv_bfloat16* Wp = W + (size_t)(n0 + srow) * K + sc;
    const unsigned a_dst = as_base + (srow * RS + sc) * 2;
    const unsigned b_dst = bs_base + (srow * RS + sc) * 2;

    const int NK = K / 32;

    // Prologue: issue stages 0,1
    #pragma unroll
    for (int st = 0; st < 2; st++) {
        cp_async16(a_dst + st * GTILE * 2,      Ap + st * 32);
        cp_async16(a_dst + st * GTILE * 2 + 16, Ap + st * 32 + 8);
        cp_async16(b_dst + st * GTILE * 2,      Wp + st * 32);
        cp_async16(b_dst + st * GTILE * 2 + 16, Wp + st * 32 + 8);
        cp_commit();
    }

    float acc[2][8][4];
    #pragma unroll
    for (int mf = 0; mf < 2; mf++)
        #pragma unroll
        for (int nf = 0; nf < 8; nf++)
            #pragma unroll
            for (int i = 0; i < 4; i++) acc[mf][nf][i] = 0.f;

    int cur = 0, nxt = 2;
    for (int it = 0; it < NK; it++) {
        if (it + 2 < NK) {
            cp_wait<1>();
        } else {
            cp_wait<0>();
        }
        __syncthreads();

        // Issue tile it+2 into buffer nxt (overwrites buffer computed at it-1;
        // the barrier above guarantees all threads finished that compute).
        if (it + 2 < NK) {
            const int ko = (it + 2) * 32;
            cp_async16(a_dst + nxt * GTILE * 2,      Ap + ko);
            cp_async16(a_dst + nxt * GTILE * 2 + 16, Ap + ko + 8);
            cp_async16(b_dst + nxt * GTILE * 2,      Wp + ko);
            cp_async16(b_dst + nxt * GTILE * 2 + 16, Wp + ko + 8);
            cp_commit();
        }

        const unsigned as_st = as_base + cur * GTILE * 2;
        const unsigned bs_st = bs_base + cur * GTILE * 2;

        #pragma unroll
        for (int ks = 0; ks < 2; ks++) {
            unsigned a[2][4];
            #pragma unroll
            for (int mf = 0; mf < 2; mf++) {
                const int r  = wm * 32 + mf * 16 + arow_in;
                const int ko = ks * 16 + akoff_in;
                ldsm_x4(a[mf][0], a[mf][1], a[mf][2], a[mf][3],
                        as_st + (r * RS + ko) * 2);
            }
            unsigned bf[4][4];
            #pragma unroll
            for (int ng = 0; ng < 4; ng++) {
                const int nr = wn * 64 + ng * 16 + brow_in;
                const int ko = ks * 16 + bkoff_in;
                ldsm_x4(bf[ng][0], bf[ng][1], bf[ng][2], bf[ng][3],
                        bs_st + (nr * RS + ko) * 2);
            }
            #pragma unroll
            for (int ng = 0; ng < 4; ng++) {
                mma_bf16(acc[0][2*ng+0], a[0], bf[ng][0], bf[ng][1]);
                mma_bf16(acc[1][2*ng+0], a[1], bf[ng][0], bf[ng][1]);
                mma_bf16(acc[0][2*ng+1], a[0], bf[ng][2], bf[ng][3]);
                mma_bf16(acc[1][2*ng+1], a[1], bf[ng][2], bf[ng][3]);
            }
        }

        cur = (cur + 1) % 3;
        nxt = (nxt + 1) % 3;
    }

    // Epilogue: select output half (whole CTA column block is in one half)
    const bool second = (n0 >= DD);
    const float* bs            = second ? bias2 : bias;
    __nv_bfloat16* Chx         = second ? Ch2 : Ch;
    const int nbase            = second ? n0 - DD : n0;

    #pragma unroll
    for (int mf = 0; mf < 2; mf++) {
        #pragma unroll
        for (int nf = 0; nf < 8; nf++) {
            const int col = nbase + wn * 64 + nf * 8 + tg * 2;
            const float bx = bs[col], by = bs[col + 1];
            #pragma unroll
            for (int half = 0; half < 2; half++) {
                const size_t grow = (size_t)(m0 + wm * 32 + mf * 16 + g + half * 8);
                float ox = acc[mf][nf][half * 2 + 0] + bx;
                float oy = acc[mf][nf][half * 2 + 1] + by;
                if (Chx) {
                    *reinterpret_cast<__nv_bfloat162*>(Chx + grow * DD + col) =
                        __floats2bfloat162_rn(ox, oy);
                } else {
                    if (R) {
                        const float2 rv = *reinterpret_cast<const float2*>(R + grow * DD + col);
                        ox += rv.x; oy += rv.y;
                    }
                    float2 o; o.x = ox; o.y = oy;
                    *reinterpret_cast<float2*>(Cf + grow * DD + col) = o;
                }
            }
        }
    }
}

// ---------------------------------------------------------------------------
// BF16 tensor-core flash attention (unchanged from round 3).
// ---------------------------------------------------------------------------
#define QSTR 72
#define OFF_Q 0
#define OFF_K (128 * QSTR)
#define OFF_V (OFF_K + 2 * 64 * QSTR)
#define OFF_P (OFF_V + 2 * 64 * QSTR)
#define SM_ELEMS (OFF_P + 128 * QSTR)
#define KVBUF (64 * QSTR)

__global__ void __launch_bounds__(128) attn_bf16_kernel(
    const __nv_bfloat16* __restrict__ Q, const __nv_bfloat16* __restrict__ K,
    const __nv_bfloat16* __restrict__ V, __nv_bfloat16* __restrict__ O)
{
    extern __shared__ __align__(16) __nv_bfloat16 smem[];
    const unsigned sm_base = (unsigned)__cvta_generic_to_shared(smem);

    const int b  = blockIdx.z;
    const int h  = blockIdx.y;
    const int q0 = blockIdx.x * 128;
    const int t  = threadIdx.x;
    const int w  = t >> 5;
    const int lane = t & 31;
    const int g  = lane >> 2;
    const int tg = lane & 3;

    const int arow_in  = (lane & 7) + ((lane >> 3) & 1) * 8;
    const int akoff_in = (lane >> 4) * 8;
    const int brow_in  = (lane & 7) + (lane >> 4) * 8;
    const int bkoff_in = ((lane >> 3) & 1) * 8;

    const __nv_bfloat16* Qb = Q + ((size_t)(b * NQ + q0)) * DD + h * HDIM;
    const __nv_bfloat16* Kb = K + ((size_t)(b * NC)) * DD + h * HDIM;
    const __nv_bfloat16* Vb = V + ((size_t)(b * NC)) * DD + h * HDIM;

    {
        #pragma unroll
        for (int c = 0; c < 8; c++)
            cp_async16(sm_base + (OFF_Q + t * QSTR + c * 8) * 2,
                       Qb + (size_t)t * DD + c * 8);
        const int r = t >> 1;
        const int cb = (t & 1) * 4;
        #pragma unroll
        for (int c = 0; c < 4; c++) {
            cp_async16(sm_base + (OFF_K + r * QSTR + (cb + c) * 8) * 2,
                       Kb + (size_t)r * DD + (cb + c) * 8);
            cp_async16(sm_base + (OFF_V + r * QSTR + (cb + c) * 8) * 2,
                       Vb + (size_t)r * DD + (cb + c) * 8);
        }
        cp_commit();
    }

    float m_i[4], l_i[4], of[2][8][4];
    #pragma unroll
    for (int i = 0; i < 4; i++) { m_i[i] = -INFINITY; l_i[i] = 0.f; }
    #pragma unroll
    for (int mf = 0; mf < 2; mf++)
        #pragma unroll
        for (int nf = 0; nf < 8; nf++)
            #pragma unroll
            for (int i = 0; i < 4; i++) of[mf][nf][i] = 0.f;

    const int NT = NC / 64;
    for (int it = 0; it < NT; it++) {
        const int cur = it & 1;
        cp_wait<0>();
        __syncthreads();

        if (it + 1 < NT) {
            const int nxt = cur ^ 1;
            const int r = t >> 1;
            const int cb = (t & 1) * 4;
            const size_t grow = (size_t)((it + 1) * 64 + r) * DD;
            #pragma unroll
            for (int c = 0; c < 4; c++) {
                cp_async16(sm_base + (OFF_K + nxt * KVBUF + r * QSTR + (cb + c) * 8) * 2,
                           Kb + grow + (cb + c) * 8);
                cp_async16(sm_base + (OFF_V + nxt * KVBUF + r * QSTR + (cb + c) * 8) * 2,
                           Vb + grow + (cb + c) * 8);
            }
            cp_commit();
        }

        const int kbase = OFF_K + cur * KVBUF;
        const int vbase = OFF_V + cur * KVBUF;

        float sf[2][8][4];
        #pragma unroll
        for (int mf = 0; mf < 2; mf++)
            #pragma unroll
            for (int nf = 0; nf < 8; nf++)
                #pragma unroll
                for (int i = 0; i < 4; i++) sf[mf][nf][i] = 0.f;

        #pragma unroll
        for (int ks = 0; ks < 4; ks++) {
            unsigned a[2][4];
            #pragma unroll
            for (int mf = 0; mf < 2; mf++) {
                const int r  = w * 32 + mf * 16 + arow_in;
                const int ko = ks * 16 + akoff_in;
                ldsm_x4(a[mf][0], a[mf][1], a[mf][2], a[mf][3],
                        sm_base + (OFF_Q + r * QSTR + ko) * 2);
            }
            unsigned bf[4][4];
            #pragma unroll
            for (int ng = 0; ng < 4; ng++) {
                const int nr = ng * 16 + brow_in;
                const int ko = ks * 16 + bkoff_in;
                ldsm_x4(bf[ng][0], bf[ng][1], bf[ng][2], bf[ng][3],
                        sm_base + (kbase + nr * QSTR + ko) * 2);
            }
            #pragma unroll
            for (int ng = 0; ng < 4; ng++) {
                mma_bf16(sf[0][2*ng+0], a[0], bf[ng][0], bf[ng][1]);
                mma_bf16(sf[1][2*ng+0], a[1], bf[ng][0], bf[ng][1]);
                mma_bf16(sf[0][2*ng+1], a[0], bf[ng][2], bf[ng][3]);
                mma_bf16(sf[1][2*ng+1], a[1], bf[ng][2], bf[ng][3]);
            }
        }

        #pragma unroll
        for (int mf = 0; mf < 2; mf++) {
            float mx0 = -INFINITY, mx1 = -INFINITY;
            #pragma unroll
            for (int nf = 0; nf < 8; nf++) {
                #pragma unroll
                for (int i = 0; i < 4; i++) sf[mf][nf][i] *= 0.125f;
                mx0 = fmaxf(mx0, fmaxf(sf[mf][nf][0], sf[mf][nf][1]));
                mx1 = fmaxf(mx1, fmaxf(sf[mf][nf][2], sf[mf][nf][3]));
            }
            mx0 = fmaxf(mx0, __shfl_xor_sync(0xffffffffu, mx0, 1));
            mx0 = fmaxf(mx0, __shfl_xor_sync(0xffffffffu, mx0, 2));
            mx1 = fmaxf(mx1, __shfl_xor_sync(0xffffffffu, mx1, 1));
            mx1 = fmaxf(mx1, __shfl_xor_sync(0xffffffffu, mx1, 2));

            const float mn0 = fmaxf(m_i[mf * 2 + 0], mx0);
            const float mn1 = fmaxf(m_i[mf * 2 + 1], mx1);
            const float f0 = __expf(m_i[mf * 2 + 0] - mn0);
            const float f1 = __expf(m_i[mf * 2 + 1] - mn1);

            const int r0 = w * 32 + mf * 16 + g;
            const int r1 = r0 + 8;
            float s0 = 0.f, s1 = 0.f;
            #pragma unroll
            for (int nf = 0; nf < 8; nf++) {
                const float p0 = __expf(sf[mf][nf][0] - mn0);
                const float p1 = __expf(sf[mf][nf][1] - mn0);
                const float p2 = __expf(sf[mf][nf][2] - mn1);
                const float p3 = __expf(sf[mf][nf][3] - mn1);
                s0 += p0 + p1;
                s1 += p2 + p3;
                *reinterpret_cast<__nv_bfloat162*>(&smem[OFF_P + r0 * QSTR + nf * 8 + tg * 2]) =
                    __floats2bfloat162_rn(p0, p1);
                *reinterpret_cast<__nv_bfloat162*>(&smem[OFF_P + r1 * QSTR + nf * 8 + tg * 2]) =
                    __floats2bfloat162_rn(p2, p3);
            }
            s0 += __shfl_xor_sync(0xffffffffu, s0, 1);
            s0 += __shfl_xor_sync(0xffffffffu, s0, 2);
            s1 += __shfl_xor_sync(0xffffffffu, s1, 1);
            s1 += __shfl_xor_sync(0xffffffffu, s1, 2);

            l_i[mf * 2 + 0] = l_i[mf * 2 + 0] * f0 + s0;
            l_i[mf * 2 + 1] = l_i[mf * 2 + 1] * f1 + s1;
            m_i[mf * 2 + 0] = mn0;
            m_i[mf * 2 + 1] = mn1;

            #pragma unroll
            for (int nf = 0; nf < 8; nf++) {
                of[mf][nf][0] *= f0; of[mf][nf][1] *= f0;
                of[mf][nf][2] *= f1; of[mf][nf][3] *= f1;
            }
        }
        __syncwarp();

        #pragma unroll
        for (int ks = 0; ks < 4; ks++) {
            unsigned a[2][4];
            #pragma unroll
            for (int mf = 0; mf < 2; mf++) {
                const int r  = w * 32 + mf * 16 + arow_in;
                const int ko = ks * 16 + akoff_in;
                ldsm_x4(a[mf][0], a[mf][1], a[mf][2], a[mf][3],
                        sm_base + (OFF_P + r * QSTR + ko) * 2);
            }
            unsigned bf[4][4];
            #pragma unroll
            for (int ng = 0; ng < 4; ng++) {
                const int kr = ks * 16 + arow_in;
                const int nc = ng * 16 + akoff_in;
                ldsm_x4_trans(bf[ng][0], bf[ng][1], bf[ng][2], bf[ng][3],
                              sm_base + (vbase + kr * QSTR + nc) * 2);
            }
            #pragma unroll
            for (int ng = 0; ng < 4; ng++) {
                mma_bf16(of[0][2*ng+0], a[0], bf[ng][0], bf[ng][1]);
                mma_bf16(of[1][2*ng+0], a[1], bf[ng][0], bf[ng][1]);
                mma_bf16(of[0][2*ng+1], a[0], bf[ng][2], bf[ng][3]);
                mma_bf16(of[1][2*ng+1], a[1], bf[ng][2], bf[ng][3]);
            }
        }
    }

    __nv_bfloat16* Ob = O + ((size_t)(b * NQ + q0)) * DD + h * HDIM;
    #pragma unroll
    for (int mf = 0; mf < 2; mf++) {
        const float inv0 = 1.f / l_i[mf * 2 + 0];
        const float inv1 = 1.f / l_i[mf * 2 + 1];
        #pragma unroll
        for (int nf = 0; nf < 8; nf++) {
            const int col = nf * 8 + tg * 2;
            const int r0 = w * 32 + mf * 16 + g;
            *reinterpret_cast<__nv_bfloat162*>(Ob + (size_t)r0 * DD + col) =
                __floats2bfloat162_rn(of[mf][nf][0] * inv0, of[mf][nf][1] * inv0);
            *reinterpret_cast<__nv_bfloat162*>(Ob + (size_t)(r0 + 8) * DD + col) =
                __floats2bfloat162_rn(of[mf][nf][2] * inv1, of[mf][nf][3] * inv1);
        }
    }
}

// ---------------------------------------------------------------------------
// Launcher
// ---------------------------------------------------------------------------
extern "C" void kernel_launch(void* const* d_in, const int* in_sizes, int n_in,
                              void* d_out, int out_size)
{
    const float* query   = (const float*)d_in[0];
    const float* context = (const float*)d_in[1];
    const float* wq = (const float*)d_in[2];
    const float* bq = (const float*)d_in[3];
    const float* wk = (const float*)d_in[4];
    const float* bk = (const float*)d_in[5];
    const float* wv = (const float*)d_in[6];
    const float* bv = (const float*)d_in[7];
    const float* wo = (const float*)d_in[8];
    const float* bo = (const float*)d_in[9];
    const float* g_q  = (const float*)d_in[10];
    const float* b_q  = (const float*)d_in[11];
    const float* g_kv = (const float*)d_in[12];
    const float* b_kv = (const float*)d_in[13];
    float* out = (float*)d_out;

    void *qn_, *qnh_, *cnh_, *qp_, *kp_, *vp_, *ao_, *wqh_, *wkvh_, *woh_;
    cudaGetSymbolAddress(&qn_,   g_qn);
    cudaGetSymbolAddress(&qnh_,  g_qnh);
    cudaGetSymbolAddress(&cnh_,  g_cnh);
    cudaGetSymbolAddress(&qp_,   g_Qp);
    cudaGetSymbolAddress(&kp_,   g_Kp);
    cudaGetSymbolAddress(&vp_,   g_Vp);
    cudaGetSymbolAddress(&ao_,   g_AO);
    cudaGetSymbolAddress(&wqh_,  g_wqh);
    cudaGetSymbolAddress(&wkvh_, g_wkvh);
    cudaGetSymbolAddress(&woh_,  g_woh);
    float* qn = (float*)qn_;
    __nv_bfloat16* qnh  = (__nv_bfloat16*)qnh_;
    __nv_bfloat16* cnh  = (__nv_bfloat16*)cnh_;
    __nv_bfloat16* Qp   = (__nv_bfloat16*)qp_;
    __nv_bfloat16* Kp   = (__nv_bfloat16*)kp_;
    __nv_bfloat16* Vp   = (__nv_bfloat16*)vp_;
    __nv_bfloat16* AO   = (__nv_bfloat16*)ao_;
    __nv_bfloat16* wqh  = (__nv_bfloat16*)wqh_;
    __nv_bfloat16* wkvh = (__nv_bfloat16*)wkvh_;
    __nv_bfloat16* woh  = (__nv_bfloat16*)woh_;

    const int attn_smem = SM_ELEMS * 2;                 // 73728 bytes
    const int gemm_smem = 6 * GTILE * 2;                // 61440 bytes
    static int configured = 0;
    if (!configured) {
        cudaFuncSetAttribute(attn_bf16_kernel,
                             cudaFuncAttributeMaxDynamicSharedMemorySize, attn_smem);
        cudaFuncSetAttribute(gemm_bf16_kernel,
                             cudaFuncAttributeMaxDynamicSharedMemorySize, gemm_smem);
        configured = 1;
    }

    // 0. Weight conversion fp32 -> bf16 (single fused launch)
    dim3 gcvt((DD * DD / 4) / 256, 4);
    cvt4_kernel<<<gcvt, 256>>>(wq, wk, wv, wo, wqh, wkvh, woh);

    // 1. LayerNorms
    ln_kernel<<<MQ, 256>>>(query,   g_q,  b_q,  qn,      qnh);
    ln_kernel<<<MC, 256>>>(context, g_kv, b_kv, nullptr, cnh);

    // 2. Projections
    dim3 gq(DD / 128, MQ / 128);        // (8, 16)   Q projection
    dim3 gkv(2 * DD / 128, MC / 128);   // (16, 64)  fused K+V projection
    gemm_bf16_kernel<<<gq,  256, gemm_smem>>>(qnh, wqh,  bq, bq, nullptr,
                                              nullptr, Qp, Qp, MQ, DD);
    gemm_bf16_kernel<<<gkv, 256, gemm_smem>>>(cnh, wkvh, bk, bv, nullptr,
                                              nullptr, Kp, Vp, MC, DD);

    // 3. Flash attention
    dim3 ga(NQ / 128, NH, BB);          // (8, 16, 2)
    attn_bf16_kernel<<<ga, 128, attn_smem>>>(Qp, Kp, Vp, AO);

    // 4. Output projection + bias + residual(qn), fp32 out
    gemm_bf16_kernel<<<gq, 256, gemm_smem>>>(AO, woh, bo, bo, qn,
                                             out, nullptr, nullptr, MQ, DD);
}

// round 6
// speedup vs baseline: 6.8734x; 1.0800x over previous
#include <cuda_runtime.h>
#include <cuda_bf16.h>
#include <math.h>

// Problem constants
#define DD   1024
#define NH   16
#define HDIM 64
#define BB   2
#define NQ   1024
#define NC   4096
#define MQ   (BB*NQ)   // 2048 query rows
#define MC   (BB*NC)   // 8192 context rows

// Scratch (static device globals: allocation-free)
__device__ float         g_qn  [(size_t)MQ*DD];   // fp32 qn (residual)
__device__ __nv_bfloat16 g_qnh [(size_t)MQ*DD];
__device__ __nv_bfloat16 g_cnh [(size_t)MC*DD];
__device__ __nv_bfloat16 g_Qp  [(size_t)MQ*DD];
__device__ __nv_bfloat16 g_Kp  [(size_t)MC*DD];
__device__ __nv_bfloat16 g_Vp  [(size_t)MC*DD];
__device__ __nv_bfloat16 g_AO  [(size_t)MQ*DD];
__device__ __nv_bfloat16 g_wqh [(size_t)DD*DD];
__device__ __nv_bfloat16 g_wkvh[(size_t)2*DD*DD]; // concat [wk; wv]
__device__ __nv_bfloat16 g_woh [(size_t)DD*DD];

// ---------------------------------------------------------------------------
// PTX helpers
// ---------------------------------------------------------------------------
__device__ __forceinline__ void mma_bf16(float* c, const unsigned* a,
                                         unsigned b0, unsigned b1) {
    asm volatile(
        "mma.sync.aligned.m16n8k16.row.col.f32.bf16.bf16.f32 "
        "{%0,%1,%2,%3}, {%4,%5,%6,%7}, {%8,%9}, {%0,%1,%2,%3};"
        : "+f"(c[0]), "+f"(c[1]), "+f"(c[2]), "+f"(c[3])
        : "r"(a[0]), "r"(a[1]), "r"(a[2]), "r"(a[3]), "r"(b0), "r"(b1));
}

__device__ __forceinline__ void ldsm_x4(unsigned& r0, unsigned& r1,
                                        unsigned& r2, unsigned& r3, unsigned addr) {
    asm volatile("ldmatrix.sync.aligned.m8n8.x4.shared.b16 {%0,%1,%2,%3}, [%4];"
                 : "=r"(r0), "=r"(r1), "=r"(r2), "=r"(r3) : "r"(addr));
}

__device__ __forceinline__ void ldsm_x4_trans(unsigned& r0, unsigned& r1,
                                              unsigned& r2, unsigned& r3, unsigned addr) {
    asm volatile("ldmatrix.sync.aligned.m8n8.x4.trans.shared.b16 {%0,%1,%2,%3}, [%4];"
                 : "=r"(r0), "=r"(r1), "=r"(r2), "=r"(r3) : "r"(addr));
}

__device__ __forceinline__ void cp_async16(unsigned dst, const void* src) {
    asm volatile("cp.async.cg.shared.global [%0], [%1], 16;" :: "r"(dst), "l"(src));
}
__device__ __forceinline__ void cp_commit() {
    asm volatile("cp.async.commit_group;");
}
template <int N>
__device__ __forceinline__ void cp_wait() {
    asm volatile("cp.async.wait_group %0;" :: "n"(N));
}

// ---------------------------------------------------------------------------
// Fused weight convert fp32 -> bf16
// ---------------------------------------------------------------------------
__global__ void __launch_bounds__(256) cvt4_kernel(
    const float* __restrict__ wq, const float* __restrict__ wk,
    const float* __restrict__ wv, const float* __restrict__ wo,
    __nv_bfloat16* __restrict__ wqh, __nv_bfloat16* __restrict__ wkvh,
    __nv_bfloat16* __restrict__ woh)
{
    const int i = (blockIdx.x * 256 + threadIdx.x) * 4;
    const int m = blockIdx.y;
    const float* s;
    __nv_bfloat16* d;
    if      (m == 0) { s = wq; d = wqh; }
    else if (m == 1) { s = wk; d = wkvh; }
    else if (m == 2) { s = wv; d = wkvh + (size_t)DD * DD; }
    else             { s = wo; d = woh; }
    const float4 v = *reinterpret_cast<const float4*>(s + i);
    __nv_bfloat162* o = reinterpret_cast<__nv_bfloat162*>(d + i);
    o[0] = __floats2bfloat162_rn(v.x, v.y);
    o[1] = __floats2bfloat162_rn(v.z, v.w);
}

// ---------------------------------------------------------------------------
// Fused LayerNorm: blocks [0,MQ) process query rows (fp32 + bf16 out),
// blocks [MQ, MQ+MC) process context rows (bf16 out only).
// ---------------------------------------------------------------------------
__global__ void __launch_bounds__(256) ln_fused_kernel(
    const float* __restrict__ query, const float* __restrict__ context,
    const float* __restrict__ gq, const float* __restrict__ bq,
    const float* __restrict__ gkv, const float* __restrict__ bkv,
    float* __restrict__ qn, __nv_bfloat16* __restrict__ qnh,
    __nv_bfloat16* __restrict__ cnh)
{
    const int bid = blockIdx.x;
    const bool isq = (bid < MQ);
    const int row = isq ? bid : bid - MQ;
    const float* x = isq ? (query + (size_t)row * DD) : (context + (size_t)row * DD);
    const float* gamma = isq ? gq : gkv;
    const float* beta  = isq ? bq : bkv;
    __nv_bfloat16* yh = isq ? (qnh + (size_t)row * DD) : (cnh + (size_t)row * DD);

    int t = threadIdx.x;
    const float4 v = reinterpret_cast<const float4*>(x)[t];
    float s  = v.x + v.y + v.z + v.w;
    float ss = v.x*v.x + v.y*v.y + v.z*v.z + v.w*v.w;
    #pragma unroll
    for (int o = 16; o > 0; o >>= 1) {
        s  += __shfl_xor_sync(0xffffffffu, s,  o);
        ss += __shfl_xor_sync(0xffffffffu, ss, o);
    }
    __shared__ float sm1[8], sm2[8];
    int w = t >> 5, l = t & 31;
    if (l == 0) { sm1[w] = s; sm2[w] = ss; }
    __syncthreads();
    if (t < 32) {
        s  = (l < 8) ? sm1[l] : 0.f;
        ss = (l < 8) ? sm2[l] : 0.f;
        #pragma unroll
        for (int o = 4; o > 0; o >>= 1) {
            s  += __shfl_xor_sync(0xffffffffu, s,  o);
            ss += __shfl_xor_sync(0xffffffffu, ss, o);
        }
        if (l == 0) { sm1[0] = s; sm2[0] = ss; }
    }
    __syncthreads();
    const float mu  = sm1[0] * (1.f / DD);
    const float var = sm2[0] * (1.f / DD) - mu * mu;
    const float inv = rsqrtf(var + 1e-5f);
    const float4 g = reinterpret_cast<const float4*>(gamma)[t];
    const float4 b = reinterpret_cast<const float4*>(beta)[t];
    float4 o;
    o.x = (v.x - mu) * inv * g.x + b.x;
    o.y = (v.y - mu) * inv * g.y + b.y;
    o.z = (v.z - mu) * inv * g.z + b.z;
    o.w = (v.w - mu) * inv * g.w + b.w;
    if (isq) reinterpret_cast<float4*>(qn + (size_t)row * DD)[t] = o;
    __nv_bfloat162* oh = reinterpret_cast<__nv_bfloat162*>(yh + t * 4);
    oh[0] = __floats2bfloat162_rn(o.x, o.y);
    oh[1] = __floats2bfloat162_rn(o.z, o.w);
}

// ---------------------------------------------------------------------------
// GEMM mainloop core (round-4 proven): 128x128x32 tile, 3-stage cp.async,
// 256 threads = 8 warps (4m x 2n), warp tile 32x64, smem stride 40 bf16.
// ---------------------------------------------------------------------------
#define RS 40
#define GTILE (128 * RS)
#define GEMM_SMEM (6 * GTILE * 2)

struct GemmCtx {
    const __nv_bfloat16 *A, *W;
    int m0, n0;
};

// Computes acc for one 128x128 tile over K=1024. gsm: 6*GTILE bf16.
__device__ __forceinline__ void gemm_mainloop(
    const GemmCtx& cx, __nv_bfloat16* gsm, float acc[2][8][4])
{
    __nv_bfloat16* As = gsm;
    __nv_bfloat16* Bs = gsm + 3 * GTILE;
    const int t    = threadIdx.x;
    const int lane = t & 31;
    const int w    = t >> 5;
    const int wm   = w >> 1;
    const int wn   = w & 1;

    const unsigned as_base = (unsigned)__cvta_generic_to_shared(As);
    const unsigned bs_base = (unsigned)__cvta_generic_to_shared(Bs);

    const int arow_in  = (lane & 7) + ((lane >> 3) & 1) * 8;
    const int akoff_in = (lane >> 4) * 8;
    const int brow_in  = (lane & 7) + (lane >> 4) * 8;
    const int bkoff_in = ((lane >> 3) & 1) * 8;

    const int srow = t >> 1;
    const int sc   = (t & 1) * 16;

    const __nv_bfloat16* Ap = cx.A + (size_t)(cx.m0 + srow) * DD + sc;
    const __nv_bfloat16* Wp = cx.W + (size_t)(cx.n0 + srow) * DD + sc;
    const unsigned a_dst = as_base + (srow * RS + sc) * 2;
    const unsigned b_dst = bs_base + (srow * RS + sc) * 2;

    const int NK = DD / 32;

    #pragma unroll
    for (int st = 0; st < 2; st++) {
        cp_async16(a_dst + st * GTILE * 2,      Ap + st * 32);
        cp_async16(a_dst + st * GTILE * 2 + 16, Ap + st * 32 + 8);
        cp_async16(b_dst + st * GTILE * 2,      Wp + st * 32);
        cp_async16(b_dst + st * GTILE * 2 + 16, Wp + st * 32 + 8);
        cp_commit();
    }

    #pragma unroll
    for (int mf = 0; mf < 2; mf++)
        #pragma unroll
        for (int nf = 0; nf < 8; nf++)
            #pragma unroll
            for (int i = 0; i < 4; i++) acc[mf][nf][i] = 0.f;

    int cur = 0, nxt = 2;
    for (int it = 0; it < NK; it++) {
        if (it + 2 < NK) {
            cp_wait<1>();
        } else {
            cp_wait<0>();
        }
        __syncthreads();

        if (it + 2 < NK) {
            const int ko = (it + 2) * 32;
            cp_async16(a_dst + nxt * GTILE * 2,      Ap + ko);
            cp_async16(a_dst + nxt * GTILE * 2 + 16, Ap + ko + 8);
            cp_async16(b_dst + nxt * GTILE * 2,      Wp + ko);
            cp_async16(b_dst + nxt * GTILE * 2 + 16, Wp + ko + 8);
            cp_commit();
        }

        const unsigned as_st = as_base + cur * GTILE * 2;
        const unsigned bs_st = bs_base + cur * GTILE * 2;

        #pragma unroll
        for (int ks = 0; ks < 2; ks++) {
            unsigned a[2][4];
            #pragma unroll
            for (int mf = 0; mf < 2; mf++) {
                const int r  = wm * 32 + mf * 16 + arow_in;
                const int ko = ks * 16 + akoff_in;
                ldsm_x4(a[mf][0], a[mf][1], a[mf][2], a[mf][3],
                        as_st + (r * RS + ko) * 2);
            }
            unsigned bf[4][4];
            #pragma unroll
            for (int ng = 0; ng < 4; ng++) {
                const int nr = wn * 64 + ng * 16 + brow_in;
                const int ko = ks * 16 + bkoff_in;
                ldsm_x4(bf[ng][0], bf[ng][1], bf[ng][2], bf[ng][3],
                        bs_st + (nr * RS + ko) * 2);
            }
            #pragma unroll
            for (int ng = 0; ng < 4; ng++) {
                mma_bf16(acc[0][2*ng+0], a[0], bf[ng][0], bf[ng][1]);
                mma_bf16(acc[1][2*ng+0], a[1], bf[ng][0], bf[ng][1]);
                mma_bf16(acc[0][2*ng+1], a[0], bf[ng][2], bf[ng][3]);
                mma_bf16(acc[1][2*ng+1], a[1], bf[ng][2], bf[ng][3]);
            }
        }

        cur = (cur + 1) % 3;
        nxt = (nxt + 1) % 3;
    }
}

// ---------------------------------------------------------------------------
// Fused Q + KV projection: grid = 1024 KV CTAs then 128 Q CTAs.
// ---------------------------------------------------------------------------
__global__ void __launch_bounds__(256) proj_fused_kernel(
    const __nv_bfloat16* __restrict__ qnh, const __nv_bfloat16* __restrict__ cnh,
    const __nv_bfloat16* __restrict__ wqh, const __nv_bfloat16* __restrict__ wkvh,
    const float* __restrict__ bq, const float* __restrict__ bk,
    const float* __restrict__ bv,
    __nv_bfloat16* __restrict__ Qp, __nv_bfloat16* __restrict__ Kp,
    __nv_bfloat16* __restrict__ Vp)
{
    extern __shared__ __align__(16) __nv_bfloat16 gsm[];

    GemmCtx cx;
    const float* bias;
    __nv_bfloat16* Co;
    int nbase;
    const int bid = blockIdx.x;
    if (bid < 1024) {
        // KV projection: cn[8192,1024] @ wkv[2048,1024]^T, 64 m-tiles x 16 n-tiles
        cx.A = cnh; cx.W = wkvh;
        cx.m0 = (bid >> 4) * 128;
        cx.n0 = (bid & 15) * 128;
        if (cx.n0 < DD) { bias = bk; Co = Kp; nbase = cx.n0; }
        else            { bias = bv; Co = Vp; nbase = cx.n0 - DD; }
    } else {
        // Q projection: qn[2048,1024] @ wq[1024,1024]^T, 16 m-tiles x 8 n-tiles
        const int i2 = bid - 1024;
        cx.A = qnh; cx.W = wqh;
        cx.m0 = (i2 >> 3) * 128;
        cx.n0 = (i2 & 7) * 128;
        bias = bq; Co = Qp; nbase = cx.n0;
    }

    float acc[2][8][4];
    gemm_mainloop(cx, gsm, acc);

    const int t = threadIdx.x, lane = t & 31, w = t >> 5;
    const int wm = w >> 1, wn = w & 1, g = lane >> 2, tg = lane & 3;

    #pragma unroll
    for (int mf = 0; mf < 2; mf++) {
        #pragma unroll
        for (int nf = 0; nf < 8; nf++) {
            const int col = nbase + wn * 64 + nf * 8 + tg * 2;
            const float bx = bias[col], by = bias[col + 1];
            #pragma unroll
            for (int half = 0; half < 2; half++) {
                const size_t grow = (size_t)(cx.m0 + wm * 32 + mf * 16 + g + half * 8);
                *reinterpret_cast<__nv_bfloat162*>(Co + grow * DD + col) =
                    __floats2bfloat162_rn(acc[mf][nf][half * 2 + 0] + bx,
                                          acc[mf][nf][half * 2 + 1] + by);
            }
        }
    }
}

// ---------------------------------------------------------------------------
// O projection + bias + residual (fp32 out)
// ---------------------------------------------------------------------------
__global__ void __launch_bounds__(256) oproj_kernel(
    const __nv_bfloat16* __restrict__ A, const __nv_bfloat16* __restrict__ W,
    const float* __restrict__ bias, const float* __restrict__ R,
    float* __restrict__ Cf)
{
    extern __shared__ __align__(16) __nv_bfloat16 gsm[];

    GemmCtx cx;
    cx.A = A; cx.W = W;
    cx.m0 = blockIdx.y * 128;
    cx.n0 = blockIdx.x * 128;

    float acc[2][8][4];
    gemm_mainloop(cx, gsm, acc);

    const int t = threadIdx.x, lane = t & 31, w = t >> 5;
    const int wm = w >> 1, wn = w & 1, g = lane >> 2, tg = lane & 3;

    #pragma unroll
    for (int mf = 0; mf < 2; mf++) {
        #pragma unroll
        for (int nf = 0; nf < 8; nf++) {
            const int col = cx.n0 + wn * 64 + nf * 8 + tg * 2;
            const float bx = bias[col], by = bias[col + 1];
            #pragma unroll
            for (int half = 0; half < 2; half++) {
                const size_t grow = (size_t)(cx.m0 + wm * 32 + mf * 16 + g + half * 8);
                const float2 rv = *reinterpret_cast<const float2*>(R + grow * DD + col);
                float2 o;
                o.x = acc[mf][nf][half * 2 + 0] + bx + rv.x;
                o.y = acc[mf][nf][half * 2 + 1] + by + rv.y;
                *reinterpret_cast<float2*>(Cf + grow * DD + col) = o;
            }
        }
    }
}

// ---------------------------------------------------------------------------
// BF16 flash attention: 256 threads = 8 warps, q-tile 128 (warp tile m16xn64),
// K/V tiles (64x64) double-buffered via cp.async, exp2-domain softmax.
// ---------------------------------------------------------------------------
#define QSTR 72
#define OFF_Q 0
#define OFF_K (128 * QSTR)
#define OFF_V (OFF_K + 2 * 64 * QSTR)
#define OFF_P (OFF_V + 2 * 64 * QSTR)
#define SM_ELEMS (OFF_P + 128 * QSTR)
#define KVBUF (64 * QSTR)
#define SSCALE 0.18033688f   /* 0.125 * log2(e) */

__global__ void __launch_bounds__(256) attn_bf16_kernel(
    const __nv_bfloat16* __restrict__ Q, const __nv_bfloat16* __restrict__ K,
    const __nv_bfloat16* __restrict__ V, __nv_bfloat16* __restrict__ O)
{
    extern __shared__ __align__(16) __nv_bfloat16 smem[];
    const unsigned sm_base = (unsigned)__cvta_generic_to_shared(smem);

    const int b  = blockIdx.z;
    const int h  = blockIdx.y;
    const int q0 = blockIdx.x * 128;
    const int t  = threadIdx.x;
    const int w  = t >> 5;           // 0..7
    const int lane = t & 31;
    const int g  = lane >> 2;
    const int tg = lane & 3;
    const int wrow = w * 16;         // warp's 16 q rows

    const int arow_in  = (lane & 7) + ((lane >> 3) & 1) * 8;
    const int akoff_in = (lane >> 4) * 8;
    const int brow_in  = (lane & 7) + (lane >> 4) * 8;
    const int bkoff_in = ((lane >> 3) & 1) * 8;

    const __nv_bfloat16* Qb = Q + ((size_t)(b * NQ + q0)) * DD + h * HDIM;
    const __nv_bfloat16* Kb = K + ((size_t)(b * NC)) * DD + h * HDIM;
    const __nv_bfloat16* Vb = V + ((size_t)(b * NC)) * DD + h * HDIM;

    // Prologue: Q (128x64) + K/V tile 0 (64x64 each)
    {
        #pragma unroll
        for (int i = t; i < 128 * 8; i += 256) {
            const int r = i >> 3, c = (i & 7) * 8;
            cp_async16(sm_base + (OFF_Q + r * QSTR + c) * 2, Qb + (size_t)r * DD + c);
        }
        #pragma unroll
        for (int i = t; i < 64 * 8; i += 256) {
            const int r = i >> 3, c = (i & 7) * 8;
            cp_async16(sm_base + (OFF_K + r * QSTR + c) * 2, Kb + (size_t)r * DD + c);
            cp_async16(sm_base + (OFF_V + r * QSTR + c) * 2, Vb + (size_t)r * DD + c);
        }
        cp_commit();
    }

    float m_i[2], l_i[2], of[8][4];
    m_i[0] = m_i[1] = -INFINITY;
    l_i[0] = l_i[1] = 0.f;
    #pragma unroll
    for (int nf = 0; nf < 8; nf++)
        #pragma unroll
        for (int i = 0; i < 4; i++) of[nf][i] = 0.f;

    const int NT = NC / 64;
    for (int it = 0; it < NT; it++) {
        const int cur = it & 1;
        cp_wait<0>();
        __syncthreads();

        if (it + 1 < NT) {
            const int nxt = cur ^ 1;
            #pragma unroll
            for (int i = t; i < 64 * 8; i += 256) {
                const int r = i >> 3, c = (i & 7) * 8;
                const size_t grow = (size_t)((it + 1) * 64 + r) * DD + c;
                cp_async16(sm_base + (OFF_K + nxt * KVBUF + r * QSTR + c) * 2, Kb + grow);
                cp_async16(sm_base + (OFF_V + nxt * KVBUF + r * QSTR + c) * 2, Vb + grow);
            }
            cp_commit();
        }

        const int kbase = OFF_K + cur * KVBUF;
        const int vbase = OFF_V + cur * KVBUF;

        // ---- S = Q K^T : warp m16 x n64 over k=64 ----
        float sf[8][4];
        #pragma unroll
        for (int nf = 0; nf < 8; nf++)
            #pragma unroll
            for (int i = 0; i < 4; i++) sf[nf][i] = 0.f;

        #pragma unroll
        for (int ks = 0; ks < 4; ks++) {
            unsigned a[4];
            ldsm_x4(a[0], a[1], a[2], a[3],
                    sm_base + (OFF_Q + (wrow + arow_in) * QSTR + ks * 16 + akoff_in) * 2);
            unsigned bf[4][4];
            #pragma unroll
            for (int ng = 0; ng < 4; ng++) {
                ldsm_x4(bf[ng][0], bf[ng][1], bf[ng][2], bf[ng][3],
                        sm_base + (kbase + (ng * 16 + brow_in) * QSTR + ks * 16 + bkoff_in) * 2);
            }
            #pragma unroll
            for (int ng = 0; ng < 4; ng++) {
                mma_bf16(sf[2*ng+0], a, bf[ng][0], bf[ng][1]);
                mma_bf16(sf[2*ng+1], a, bf[ng][2], bf[ng][3]);
            }
        }

        // ---- online softmax (log2 domain) ----
        {
            float mx0 = -INFINITY, mx1 = -INFINITY;
            #pragma unroll
            for (int nf = 0; nf < 8; nf++) {
                #pragma unroll
                for (int i = 0; i < 4; i++) sf[nf][i] *= SSCALE;
                mx0 = fmaxf(mx0, fmaxf(sf[nf][0], sf[nf][1]));
                mx1 = fmaxf(mx1, fmaxf(sf[nf][2], sf[nf][3]));
            }
            mx0 = fmaxf(mx0, __shfl_xor_sync(0xffffffffu, mx0, 1));
            mx0 = fmaxf(mx0, __shfl_xor_sync(0xffffffffu, mx0, 2));
            mx1 = fmaxf(mx1, __shfl_xor_sync(0xffffffffu, mx1, 1));
            mx1 = fmaxf(mx1, __shfl_xor_sync(0xffffffffu, mx1, 2));

            const float mn0 = fmaxf(m_i[0], mx0);
            const float mn1 = fmaxf(m_i[1], mx1);
            const float f0 = exp2f(m_i[0] - mn0);
            const float f1 = exp2f(m_i[1] - mn1);

            const int r0 = wrow + g;
            const int r1 = r0 + 8;
            float s0 = 0.f, s1 = 0.f;
            #pragma unroll
            for (int nf = 0; nf < 8; nf++) {
                const float p0 = exp2f(sf[nf][0] - mn0);
                const float p1 = exp2f(sf[nf][1] - mn0);
                const float p2 = exp2f(sf[nf][2] - mn1);
                const float p3 = exp2f(sf[nf][3] - mn1);
                s0 += p0 + p1;
                s1 += p2 + p3;
                *reinterpret_cast<__nv_bfloat162*>(&smem[OFF_P + r0 * QSTR + nf * 8 + tg * 2]) =
                    __floats2bfloat162_rn(p0, p1);
                *reinterpret_cast<__nv_bfloat162*>(&smem[OFF_P + r1 * QSTR + nf * 8 + tg * 2]) =
                    __floats2bfloat162_rn(p2, p3);
            }
            s0 += __shfl_xor_sync(0xffffffffu, s0, 1);
            s0 += __shfl_xor_sync(0xffffffffu, s0, 2);
            s1 += __shfl_xor_sync(0xffffffffu, s1, 1);
            s1 += __shfl_xor_sync(0xffffffffu, s1, 2);

            l_i[0] = l_i[0] * f0 + s0;
            l_i[1] = l_i[1] * f1 + s1;
            m_i[0] = mn0;
            m_i[1] = mn1;

            #pragma unroll
            for (int nf = 0; nf < 8; nf++) {
                of[nf][0] *= f0; of[nf][1] *= f0;
                of[nf][2] *= f1; of[nf][3] *= f1;
            }
        }
        __syncwarp();   // Ps rows are warp-private

        // ---- O += P V : warp m16 x n64 over k=64 ----
        #pragma unroll
        for (int ks = 0; ks < 4; ks++) {
            unsigned a[4];
            ldsm_x4(a[0], a[1], a[2], a[3],
                    sm_base + (OFF_P + (wrow + arow_in) * QSTR + ks * 16 + akoff_in) * 2);
            unsigned bf[4][4];
            #pragma unroll
            for (int ng = 0; ng < 4; ng++) {
                ldsm_x4_trans(bf[ng][0], bf[ng][1], bf[ng][2], bf[ng][3],
                              sm_base + (vbase + (ks * 16 + arow_in) * QSTR + ng * 16 + akoff_in) * 2);
            }
            #pragma unroll
            for (int ng = 0; ng < 4; ng++) {
                mma_bf16(of[2*ng+0], a, bf[ng][0], bf[ng][1]);
                mma_bf16(of[2*ng+1], a, bf[ng][2], bf[ng][3]);
            }
        }
    }

    // Epilogue
    __nv_bfloat16* Ob = O + ((size_t)(b * NQ + q0)) * DD + h * HDIM;
    const float inv0 = 1.f / l_i[0];
    const float inv1 = 1.f / l_i[1];
    #pragma unroll
    for (int nf = 0; nf < 8; nf++) {
        const int col = nf * 8 + tg * 2;
        const int r0 = wrow + g;
        *reinterpret_cast<__nv_bfloat162*>(Ob + (size_t)r0 * DD + col) =
            __floats2bfloat162_rn(of[nf][0] * inv0, of[nf][1] * inv0);
        *reinterpret_cast<__nv_bfloat162*>(Ob + (size_t)(r0 + 8) * DD + col) =
            __floats2bfloat162_rn(of[nf][2] * inv1, of[nf][3] * inv1);
    }
}

// ---------------------------------------------------------------------------
// Launcher
// ---------------------------------------------------------------------------
extern "C" void kernel_launch(void* const* d_in, const int* in_sizes, int n_in,
                              void* d_out, int out_size)
{
    const float* query   = (const float*)d_in[0];
    const float* context = (const float*)d_in[1];
    const float* wq = (const float*)d_in[2];
    const float* bq = (const float*)d_in[3];
    const float* wk = (const float*)d_in[4];
    const float* bk = (const float*)d_in[5];
    const float* wv = (const float*)d_in[6];
    const float* bv = (const float*)d_in[7];
    const float* wo = (const float*)d_in[8];
    const float* bo = (const float*)d_in[9];
    const float* g_q  = (const float*)d_in[10];
    const float* b_q  = (const float*)d_in[11];
    const float* g_kv = (const float*)d_in[12];
    const float* b_kv = (const float*)d_in[13];
    float* out = (float*)d_out;

    void *qn_, *qnh_, *cnh_, *qp_, *kp_, *vp_, *ao_, *wqh_, *wkvh_, *woh_;
    cudaGetSymbolAddress(&qn_,   g_qn);
    cudaGetSymbolAddress(&qnh_,  g_qnh);
    cudaGetSymbolAddress(&cnh_,  g_cnh);
    cudaGetSymbolAddress(&qp_,   g_Qp);
    cudaGetSymbolAddress(&kp_,   g_Kp);
    cudaGetSymbolAddress(&vp_,   g_Vp);
    cudaGetSymbolAddress(&ao_,   g_AO);
    cudaGetSymbolAddress(&wqh_,  g_wqh);
    cudaGetSymbolAddress(&wkvh_, g_wkvh);
    cudaGetSymbolAddress(&woh_,  g_woh);
    float* qn = (float*)qn_;
    __nv_bfloat16* qnh  = (__nv_bfloat16*)qnh_;
    __nv_bfloat16* cnh  = (__nv_bfloat16*)cnh_;
    __nv_bfloat16* Qp   = (__nv_bfloat16*)qp_;
    __nv_bfloat16* Kp   = (__nv_bfloat16*)kp_;
    __nv_bfloat16* Vp   = (__nv_bfloat16*)vp_;
    __nv_bfloat16* AO   = (__nv_bfloat16*)ao_;
    __nv_bfloat16* wqh  = (__nv_bfloat16*)wqh_;
    __nv_bfloat16* wkvh = (__nv_bfloat16*)wkvh_;
    __nv_bfloat16* woh  = (__nv_bfloat16*)woh_;

    const int attn_smem = SM_ELEMS * 2;      // 73728 bytes
    static int configured = 0;
    if (!configured) {
        cudaFuncSetAttribute(attn_bf16_kernel,
                             cudaFuncAttributeMaxDynamicSharedMemorySize, attn_smem);
        cudaFuncSetAttribute(proj_fused_kernel,
                             cudaFuncAttributeMaxDynamicSharedMemorySize, GEMM_SMEM);
        cudaFuncSetAttribute(oproj_kernel,
                             cudaFuncAttributeMaxDynamicSharedMemorySize, GEMM_SMEM);
        configured = 1;
    }

    // 0. Weight conversion fp32 -> bf16
    dim3 gcvt((DD * DD / 4) / 256, 4);
    cvt4_kernel<<<gcvt, 256>>>(wq, wk, wv, wo, wqh, wkvh, woh);

    // 1. Fused LayerNorms
    ln_fused_kernel<<<MQ + MC, 256>>>(query, context, g_q, b_q, g_kv, b_kv,
                                      qn, qnh, cnh);

    // 2. Fused Q + KV projections (one launch, 1152 CTAs)
    proj_fused_kernel<<<1152, 256, GEMM_SMEM>>>(qnh, cnh, wqh, wkvh,
                                                bq, bk, bv, Qp, Kp, Vp);

    // 3. Flash attention (8 warps/CTA)
    dim3 ga(NQ / 128, NH, BB);          // (8, 16, 2)
    attn_bf16_kernel<<<ga, 256, attn_smem>>>(Qp, Kp, Vp, AO);

    // 4. Output projection + bias + residual(qn), fp32 out
    dim3 go(DD / 128, MQ / 128);        // (8, 16)
    oproj_kernel<<<go, 256, GEMM_SMEM>>>(AO, woh, bo, qn, out);
}

// round 7
// speedup vs baseline: 7.0648x; 1.0279x over previous
#include <cuda_runtime.h>
#include <cuda_bf16.h>
#include <math.h>

// Problem constants
#define DD   1024
#define NH   16
#define HDIM 64
#define BB   2
#define NQ   1024
#define NC   4096
#define MQ   (BB*NQ)   // 2048 query rows
#define MC   (BB*NC)   // 8192 context rows

// Scratch (static device globals: allocation-free)
__device__ float         g_qn  [(size_t)MQ*DD];   // fp32 qn (residual)
__device__ __nv_bfloat16 g_qnh [(size_t)MQ*DD];
__device__ __nv_bfloat16 g_cnh [(size_t)MC*DD];
__device__ __nv_bfloat16 g_Qp  [(size_t)MQ*DD];
__device__ __nv_bfloat16 g_Kp  [(size_t)MC*DD];
__device__ __nv_bfloat16 g_Vp  [(size_t)MC*DD];
__device__ __nv_bfloat16 g_AO  [(size_t)MQ*DD];
__device__ __nv_bfloat16 g_wqh [(size_t)DD*DD];
__device__ __nv_bfloat16 g_wkvh[(size_t)2*DD*DD]; // concat [wk; wv]
__device__ __nv_bfloat16 g_woh [(size_t)DD*DD];

// ---------------------------------------------------------------------------
// PTX helpers
// ---------------------------------------------------------------------------
__device__ __forceinline__ void mma_bf16(float* c, const unsigned* a,
                                         unsigned b0, unsigned b1) {
    asm volatile(
        "mma.sync.aligned.m16n8k16.row.col.f32.bf16.bf16.f32 "
        "{%0,%1,%2,%3}, {%4,%5,%6,%7}, {%8,%9}, {%0,%1,%2,%3};"
        : "+f"(c[0]), "+f"(c[1]), "+f"(c[2]), "+f"(c[3])
        : "r"(a[0]), "r"(a[1]), "r"(a[2]), "r"(a[3]), "r"(b0), "r"(b1));
}

__device__ __forceinline__ void ldsm_x4(unsigned& r0, unsigned& r1,
                                        unsigned& r2, unsigned& r3, unsigned addr) {
    asm volatile("ldmatrix.sync.aligned.m8n8.x4.shared.b16 {%0,%1,%2,%3}, [%4];"
                 : "=r"(r0), "=r"(r1), "=r"(r2), "=r"(r3) : "r"(addr));
}

__device__ __forceinline__ void ldsm_x4_trans(unsigned& r0, unsigned& r1,
                                              unsigned& r2, unsigned& r3, unsigned addr) {
    asm volatile("ldmatrix.sync.aligned.m8n8.x4.trans.shared.b16 {%0,%1,%2,%3}, [%4];"
                 : "=r"(r0), "=r"(r1), "=r"(r2), "=r"(r3) : "r"(addr));
}

__device__ __forceinline__ void cp_async16(unsigned dst, const void* src) {
    asm volatile("cp.async.cg.shared.global [%0], [%1], 16;" :: "r"(dst), "l"(src));
}
__device__ __forceinline__ void cp_commit() {
    asm volatile("cp.async.commit_group;");
}
template <int N>
__device__ __forceinline__ void cp_wait() {
    asm volatile("cp.async.wait_group %0;" :: "n"(N));
}

// pack two fp32 into bf16x2 register (lo, hi)
__device__ __forceinline__ unsigned pack_bf16x2(float lo, float hi) {
    __nv_bfloat162 h = __floats2bfloat162_rn(lo, hi);
    return *reinterpret_cast<unsigned*>(&h);
}

// ---------------------------------------------------------------------------
// Fused weight convert fp32 -> bf16
// ---------------------------------------------------------------------------
__global__ void __launch_bounds__(256) cvt4_kernel(
    const float* __restrict__ wq, const float* __restrict__ wk,
    const float* __restrict__ wv, const float* __restrict__ wo,
    __nv_bfloat16* __restrict__ wqh, __nv_bfloat16* __restrict__ wkvh,
    __nv_bfloat16* __restrict__ woh)
{
    const int i = (blockIdx.x * 256 + threadIdx.x) * 4;
    const int m = blockIdx.y;
    const float* s;
    __nv_bfloat16* d;
    if      (m == 0) { s = wq; d = wqh; }
    else if (m == 1) { s = wk; d = wkvh; }
    else if (m == 2) { s = wv; d = wkvh + (size_t)DD * DD; }
    else             { s = wo; d = woh; }
    const float4 v = *reinterpret_cast<const float4*>(s + i);
    __nv_bfloat162* o = reinterpret_cast<__nv_bfloat162*>(d + i);
    o[0] = __floats2bfloat162_rn(v.x, v.y);
    o[1] = __floats2bfloat162_rn(v.z, v.w);
}

// ---------------------------------------------------------------------------
// Fused LayerNorm
// ---------------------------------------------------------------------------
__global__ void __launch_bounds__(256) ln_fused_kernel(
    const float* __restrict__ query, const float* __restrict__ context,
    const float* __restrict__ gq, const float* __restrict__ bq,
    const float* __restrict__ gkv, const float* __restrict__ bkv,
    float* __restrict__ qn, __nv_bfloat16* __restrict__ qnh,
    __nv_bfloat16* __restrict__ cnh)
{
    const int bid = blockIdx.x;
    const bool isq = (bid < MQ);
    const int row = isq ? bid : bid - MQ;
    const float* x = isq ? (query + (size_t)row * DD) : (context + (size_t)row * DD);
    const float* gamma = isq ? gq : gkv;
    const float* beta  = isq ? bq : bkv;
    __nv_bfloat16* yh = isq ? (qnh + (size_t)row * DD) : (cnh + (size_t)row * DD);

    int t = threadIdx.x;
    const float4 v = reinterpret_cast<const float4*>(x)[t];
    float s  = v.x + v.y + v.z + v.w;
    float ss = v.x*v.x + v.y*v.y + v.z*v.z + v.w*v.w;
    #pragma unroll
    for (int o = 16; o > 0; o >>= 1) {
        s  += __shfl_xor_sync(0xffffffffu, s,  o);
        ss += __shfl_xor_sync(0xffffffffu, ss, o);
    }
    __shared__ float sm1[8], sm2[8];
    int w = t >> 5, l = t & 31;
    if (l == 0) { sm1[w] = s; sm2[w] = ss; }
    __syncthreads();
    if (t < 32) {
        s  = (l < 8) ? sm1[l] : 0.f;
        ss = (l < 8) ? sm2[l] : 0.f;
        #pragma unroll
        for (int o = 4; o > 0; o >>= 1) {
            s  += __shfl_xor_sync(0xffffffffu, s,  o);
            ss += __shfl_xor_sync(0xffffffffu, ss, o);
        }
        if (l == 0) { sm1[0] = s; sm2[0] = ss; }
    }
    __syncthreads();
    const float mu  = sm1[0] * (1.f / DD);
    const float var = sm2[0] * (1.f / DD) - mu * mu;
    const float inv = rsqrtf(var + 1e-5f);
    const float4 g = reinterpret_cast<const float4*>(gamma)[t];
    const float4 b = reinterpret_cast<const float4*>(beta)[t];
    float4 o;
    o.x = (v.x - mu) * inv * g.x + b.x;
    o.y = (v.y - mu) * inv * g.y + b.y;
    o.z = (v.z - mu) * inv * g.z + b.z;
    o.w = (v.w - mu) * inv * g.w + b.w;
    if (isq) reinterpret_cast<float4*>(qn + (size_t)row * DD)[t] = o;
    __nv_bfloat162* oh = reinterpret_cast<__nv_bfloat162*>(yh + t * 4);
    oh[0] = __floats2bfloat162_rn(o.x, o.y);
    oh[1] = __floats2bfloat162_rn(o.z, o.w);
}

// ---------------------------------------------------------------------------
// GEMM mainloop core: 128x128x32 tile, 4-stage cp.async pipeline,
// 256 threads = 8 warps (4m x 2n), warp tile 32x64, smem stride 40 bf16.
// ---------------------------------------------------------------------------
#define RS 40
#define GTILE (128 * RS)
#define GSTAGES 4
#define GEMM_SMEM (2 * GSTAGES * GTILE * 2)

struct GemmCtx {
    const __nv_bfloat16 *A, *W;
    int m0, n0;
};

__device__ __forceinline__ void gemm_mainloop(
    const GemmCtx& cx, __nv_bfloat16* gsm, float acc[2][8][4])
{
    __nv_bfloat16* As = gsm;
    __nv_bfloat16* Bs = gsm + GSTAGES * GTILE;
    const int t    = threadIdx.x;
    const int lane = t & 31;
    const int w    = t >> 5;
    const int wm   = w >> 1;
    const int wn   = w & 1;

    const unsigned as_base = (unsigned)__cvta_generic_to_shared(As);
    const unsigned bs_base = (unsigned)__cvta_generic_to_shared(Bs);

    const int arow_in  = (lane & 7) + ((lane >> 3) & 1) * 8;
    const int akoff_in = (lane >> 4) * 8;
    const int brow_in  = (lane & 7) + (lane >> 4) * 8;
    const int bkoff_in = ((lane >> 3) & 1) * 8;

    const int srow = t >> 1;
    const int sc   = (t & 1) * 16;

    const __nv_bfloat16* Ap = cx.A + (size_t)(cx.m0 + srow) * DD + sc;
    const __nv_bfloat16* Wp = cx.W + (size_t)(cx.n0 + srow) * DD + sc;
    const unsigned a_dst = as_base + (srow * RS + sc) * 2;
    const unsigned b_dst = bs_base + (srow * RS + sc) * 2;

    const int NK = DD / 32;

    #pragma unroll
    for (int st = 0; st < GSTAGES - 1; st++) {
        cp_async16(a_dst + st * GTILE * 2,      Ap + st * 32);
        cp_async16(a_dst + st * GTILE * 2 + 16, Ap + st * 32 + 8);
        cp_async16(b_dst + st * GTILE * 2,      Wp + st * 32);
        cp_async16(b_dst + st * GTILE * 2 + 16, Wp + st * 32 + 8);
        cp_commit();
    }

    #pragma unroll
    for (int mf = 0; mf < 2; mf++)
        #pragma unroll
        for (int nf = 0; nf < 8; nf++)
            #pragma unroll
            for (int i = 0; i < 4; i++) acc[mf][nf][i] = 0.f;

    int cur = 0, nxt = GSTAGES - 1;
    for (int it = 0; it < NK; it++) {
        if (it + 2 < NK)      cp_wait<2>();
        else if (it + 1 < NK) cp_wait<1>();
        else                  cp_wait<0>();
        __syncthreads();

        // Issue tile it+3 into buffer nxt (== (it-1)%4, compute done at barrier)
        if (it + GSTAGES - 1 < NK) {
            const int ko = (it + GSTAGES - 1) * 32;
            cp_async16(a_dst + nxt * GTILE * 2,      Ap + ko);
            cp_async16(a_dst + nxt * GTILE * 2 + 16, Ap + ko + 8);
            cp_async16(b_dst + nxt * GTILE * 2,      Wp + ko);
            cp_async16(b_dst + nxt * GTILE * 2 + 16, Wp + ko + 8);
            cp_commit();
        }

        const unsigned as_st = as_base + cur * GTILE * 2;
        const unsigned bs_st = bs_base + cur * GTILE * 2;

        #pragma unroll
        for (int ks = 0; ks < 2; ks++) {
            unsigned a[2][4];
            #pragma unroll
            for (int mf = 0; mf < 2; mf++) {
                const int r  = wm * 32 + mf * 16 + arow_in;
                const int ko = ks * 16 + akoff_in;
                ldsm_x4(a[mf][0], a[mf][1], a[mf][2], a[mf][3],
                        as_st + (r * RS + ko) * 2);
            }
            unsigned bf[4][4];
            #pragma unroll
            for (int ng = 0; ng < 4; ng++) {
                const int nr = wn * 64 + ng * 16 + brow_in;
                const int ko = ks * 16 + bkoff_in;
                ldsm_x4(bf[ng][0], bf[ng][1], bf[ng][2], bf[ng][3],
                        bs_st + (nr * RS + ko) * 2);
            }
            #pragma unroll
            for (int ng = 0; ng < 4; ng++) {
                mma_bf16(acc[0][2*ng+0], a[0], bf[ng][0], bf[ng][1]);
                mma_bf16(acc[1][2*ng+0], a[1], bf[ng][0], bf[ng][1]);
                mma_bf16(acc[0][2*ng+1], a[0], bf[ng][2], bf[ng][3]);
                mma_bf16(acc[1][2*ng+1], a[1], bf[ng][2], bf[ng][3]);
            }
        }

        cur = (cur + 1) & (GSTAGES - 1);
        nxt = (nxt + 1) & (GSTAGES - 1);
    }
}

// ---------------------------------------------------------------------------
// Fused Q + KV projection: grid = 1024 KV CTAs then 128 Q CTAs.
// ---------------------------------------------------------------------------
__global__ void __launch_bounds__(256) proj_fused_kernel(
    const __nv_bfloat16* __restrict__ qnh, const __nv_bfloat16* __restrict__ cnh,
    const __nv_bfloat16* __restrict__ wqh, const __nv_bfloat16* __restrict__ wkvh,
    const float* __restrict__ bq, const float* __restrict__ bk,
    const float* __restrict__ bv,
    __nv_bfloat16* __restrict__ Qp, __nv_bfloat16* __restrict__ Kp,
    __nv_bfloat16* __restrict__ Vp)
{
    extern __shared__ __align__(16) __nv_bfloat16 gsm[];

    GemmCtx cx;
    const float* bias;
    __nv_bfloat16* Co;
    int nbase;
    const int bid = blockIdx.x;
    if (bid < 1024) {
        cx.A = cnh; cx.W = wkvh;
        cx.m0 = (bid >> 4) * 128;
        cx.n0 = (bid & 15) * 128;
        if (cx.n0 < DD) { bias = bk; Co = Kp; nbase = cx.n0; }
        else            { bias = bv; Co = Vp; nbase = cx.n0 - DD; }
    } else {
        const int i2 = bid - 1024;
        cx.A = qnh; cx.W = wqh;
        cx.m0 = (i2 >> 3) * 128;
        cx.n0 = (i2 & 7) * 128;
        bias = bq; Co = Qp; nbase = cx.n0;
    }

    float acc[2][8][4];
    gemm_mainloop(cx, gsm, acc);

    const int t = threadIdx.x, lane = t & 31, w = t >> 5;
    const int wm = w >> 1, wn = w & 1, g = lane >> 2, tg = lane & 3;

    #pragma unroll
    for (int mf = 0; mf < 2; mf++) {
        #pragma unroll
        for (int nf = 0; nf < 8; nf++) {
            const int col = nbase + wn * 64 + nf * 8 + tg * 2;
            const float bx = bias[col], by = bias[col + 1];
            #pragma unroll
            for (int half = 0; half < 2; half++) {
                const size_t grow = (size_t)(cx.m0 + wm * 32 + mf * 16 + g + half * 8);
                *reinterpret_cast<__nv_bfloat162*>(Co + grow * DD + col) =
                    __floats2bfloat162_rn(acc[mf][nf][half * 2 + 0] + bx,
                                          acc[mf][nf][half * 2 + 1] + by);
            }
        }
    }
}

// ---------------------------------------------------------------------------
// O projection + bias + residual (fp32 out)
// ---------------------------------------------------------------------------
__global__ void __launch_bounds__(256) oproj_kernel(
    const __nv_bfloat16* __restrict__ A, const __nv_bfloat16* __restrict__ W,
    const float* __restrict__ bias, const float* __restrict__ R,
    float* __restrict__ Cf)
{
    extern __shared__ __align__(16) __nv_bfloat16 gsm[];

    GemmCtx cx;
    cx.A = A; cx.W = W;
    cx.m0 = blockIdx.y * 128;
    cx.n0 = blockIdx.x * 128;

    float acc[2][8][4];
    gemm_mainloop(cx, gsm, acc);

    const int t = threadIdx.x, lane = t & 31, w = t >> 5;
    const int wm = w >> 1, wn = w & 1, g = lane >> 2, tg = lane & 3;

    #pragma unroll
    for (int mf = 0; mf < 2; mf++) {
        #pragma unroll
        for (int nf = 0; nf < 8; nf++) {
            const int col = cx.n0 + wn * 64 + nf * 8 + tg * 2;
            const float bx = bias[col], by = bias[col + 1];
            #pragma unroll
            for (int half = 0; half < 2; half++) {
                const size_t grow = (size_t)(cx.m0 + wm * 32 + mf * 16 + g + half * 8);
                const float2 rv = *reinterpret_cast<const float2*>(R + grow * DD + col);
                float2 o;
                o.x = acc[mf][nf][half * 2 + 0] + bx + rv.x;
                o.y = acc[mf][nf][half * 2 + 1] + by + rv.y;
                *reinterpret_cast<float2*>(Cf + grow * DD + col) = o;
            }
        }
    }
}

// ---------------------------------------------------------------------------
// BF16 flash attention: 256 threads = 8 warps, q-tile 128 (warp tile m16xn64),
// K/V tiles (64x64) double-buffered via cp.async, P kept in registers
// (C-fragment == A-fragment identity), exp2-domain softmax with raw-unit m_i.
// ---------------------------------------------------------------------------
#define QSTR 72
#define OFF_Q 0
#define OFF_K (128 * QSTR)
#define OFF_V (OFF_K + 2 * 64 * QSTR)
#define SM_ELEMS (OFF_V + 2 * 64 * QSTR)
#define KVBUF (64 * QSTR)
#define SSCALE 0.18033688f   /* 0.125 * log2(e) */

__global__ void __launch_bounds__(256) attn_bf16_kernel(
    const __nv_bfloat16* __restrict__ Q, const __nv_bfloat16* __restrict__ K,
    const __nv_bfloat16* __restrict__ V, __nv_bfloat16* __restrict__ O)
{
    extern __shared__ __align__(16) __nv_bfloat16 smem[];
    const unsigned sm_base = (unsigned)__cvta_generic_to_shared(smem);

    const int b  = blockIdx.z;
    const int h  = blockIdx.y;
    const int q0 = blockIdx.x * 128;
    const int t  = threadIdx.x;
    const int w  = t >> 5;           // 0..7
    const int lane = t & 31;
    const int g  = lane >> 2;
    const int tg = lane & 3;
    const int wrow = w * 16;         // warp's 16 q rows

    const int arow_in  = (lane & 7) + ((lane >> 3) & 1) * 8;
    const int akoff_in = (lane >> 4) * 8;
    const int brow_in  = (lane & 7) + (lane >> 4) * 8;
    const int bkoff_in = ((lane >> 3) & 1) * 8;

    const __nv_bfloat16* Qb = Q + ((size_t)(b * NQ + q0)) * DD + h * HDIM;
    const __nv_bfloat16* Kb = K + ((size_t)(b * NC)) * DD + h * HDIM;
    const __nv_bfloat16* Vb = V + ((size_t)(b * NC)) * DD + h * HDIM;

    // Prologue: Q (128x64) + K/V tile 0 (64x64 each)
    {
        #pragma unroll
        for (int i = t; i < 128 * 8; i += 256) {
            const int r = i >> 3, c = (i & 7) * 8;
            cp_async16(sm_base + (OFF_Q + r * QSTR + c) * 2, Qb + (size_t)r * DD + c);
        }
        #pragma unroll
        for (int i = t; i < 64 * 8; i += 256) {
            const int r = i >> 3, c = (i & 7) * 8;
            cp_async16(sm_base + (OFF_K + r * QSTR + c) * 2, Kb + (size_t)r * DD + c);
            cp_async16(sm_base + (OFF_V + r * QSTR + c) * 2, Vb + (size_t)r * DD + c);
        }
        cp_commit();
    }

    float m_i[2], l_i[2], of[8][4];
    m_i[0] = m_i[1] = -INFINITY;
    l_i[0] = l_i[1] = 0.f;
    #pragma unroll
    for (int nf = 0; nf < 8; nf++)
        #pragma unroll
        for (int i = 0; i < 4; i++) of[nf][i] = 0.f;

    const int NT = NC / 64;
    for (int it = 0; it < NT; it++) {
        const int cur = it & 1;
        cp_wait<0>();
        __syncthreads();

        if (it + 1 < NT) {
            const int nxt = cur ^ 1;
            #pragma unroll
            for (int i = t; i < 64 * 8; i += 256) {
                const int r = i >> 3, c = (i & 7) * 8;
                const size_t grow = (size_t)((it + 1) * 64 + r) * DD + c;
                cp_async16(sm_base + (OFF_K + nxt * KVBUF + r * QSTR + c) * 2, Kb + grow);
                cp_async16(sm_base + (OFF_V + nxt * KVBUF + r * QSTR + c) * 2, Vb + grow);
            }
            cp_commit();
        }

        const int kbase = OFF_K + cur * KVBUF;
        const int vbase = OFF_V + cur * KVBUF;

        // ---- S = Q K^T : warp m16 x n64 over k=64 (raw scores) ----
        float sf[8][4];
        #pragma unroll
        for (int nf = 0; nf < 8; nf++)
            #pragma unroll
            for (int i = 0; i < 4; i++) sf[nf][i] = 0.f;

        #pragma unroll
        for (int ks = 0; ks < 4; ks++) {
            unsigned a[4];
            ldsm_x4(a[0], a[1], a[2], a[3],
                    sm_base + (OFF_Q + (wrow + arow_in) * QSTR + ks * 16 + akoff_in) * 2);
            unsigned bf[4][4];
            #pragma unroll
            for (int ng = 0; ng < 4; ng++) {
                ldsm_x4(bf[ng][0], bf[ng][1], bf[ng][2], bf[ng][3],
                        sm_base + (kbase + (ng * 16 + brow_in) * QSTR + ks * 16 + bkoff_in) * 2);
            }
            #pragma unroll
            for (int ng = 0; ng < 4; ng++) {
                mma_bf16(sf[2*ng+0], a, bf[ng][0], bf[ng][1]);
                mma_bf16(sf[2*ng+1], a, bf[ng][2], bf[ng][3]);
            }
        }

        // ---- online softmax; P packed directly into A-fragments ----
        unsigned pa[4][4];
        {
            float mx0 = -INFINITY, mx1 = -INFINITY;
            #pragma unroll
            for (int nf = 0; nf < 8; nf++) {
                mx0 = fmaxf(mx0, fmaxf(sf[nf][0], sf[nf][1]));
                mx1 = fmaxf(mx1, fmaxf(sf[nf][2], sf[nf][3]));
            }
            mx0 = fmaxf(mx0, __shfl_xor_sync(0xffffffffu, mx0, 1));
            mx0 = fmaxf(mx0, __shfl_xor_sync(0xffffffffu, mx0, 2));
            mx1 = fmaxf(mx1, __shfl_xor_sync(0xffffffffu, mx1, 1));
            mx1 = fmaxf(mx1, __shfl_xor_sync(0xffffffffu, mx1, 2));

            const float mn0 = fmaxf(m_i[0], mx0);   // raw units
            const float mn1 = fmaxf(m_i[1], mx1);
            const float f0 = exp2f((m_i[0] - mn0) * SSCALE);
            const float f1 = exp2f((m_i[1] - mn1) * SSCALE);
            const float c0 = mn0 * SSCALE;
            const float c1 = mn1 * SSCALE;

            float s0 = 0.f, s1 = 0.f;
            #pragma unroll
            for (int nf = 0; nf < 8; nf++) {
                const float p0 = exp2f(fmaf(sf[nf][0], SSCALE, -c0));
                const float p1 = exp2f(fmaf(sf[nf][1], SSCALE, -c0));
                const float p2 = exp2f(fmaf(sf[nf][2], SSCALE, -c1));
                const float p3 = exp2f(fmaf(sf[nf][3], SSCALE, -c1));
                s0 += p0 + p1;
                s1 += p2 + p3;
                const int ks = nf >> 1, hf = nf & 1;
                pa[ks][hf * 2 + 0] = pack_bf16x2(p0, p1);   // row g
                pa[ks][hf * 2 + 1] = pack_bf16x2(p2, p3);   // row g+8
            }
            s0 += __shfl_xor_sync(0xffffffffu, s0, 1);
            s0 += __shfl_xor_sync(0xffffffffu, s0, 2);
            s1 += __shfl_xor_sync(0xffffffffu, s1, 1);
            s1 += __shfl_xor_sync(0xffffffffu, s1, 2);

            l_i[0] = l_i[0] * f0 + s0;
            l_i[1] = l_i[1] * f1 + s1;
            m_i[0] = mn0;
            m_i[1] = mn1;

            #pragma unroll
            for (int nf = 0; nf < 8; nf++) {
                of[nf][0] *= f0; of[nf][1] *= f0;
                of[nf][2] *= f1; of[nf][3] *= f1;
            }
        }

        // ---- O += P V : P from registers, V via trans ldmatrix ----
        #pragma unroll
        for (int ks = 0; ks < 4; ks++) {
            unsigned bf[4][4];
            #pragma unroll
            for (int ng = 0; ng < 4; ng++) {
                ldsm_x4_trans(bf[ng][0], bf[ng][1], bf[ng][2], bf[ng][3],
                              sm_base + (vbase + (ks * 16 + arow_in) * QSTR + ng * 16 + akoff_in) * 2);
            }
            #pragma unroll
            for (int ng = 0; ng < 4; ng++) {
                mma_bf16(of[2*ng+0], pa[ks], bf[ng][0], bf[ng][1]);
                mma_bf16(of[2*ng+1], pa[ks], bf[ng][2], bf[ng][3]);
            }
        }
    }

    // Epilogue
    __nv_bfloat16* Ob = O + ((size_t)(b * NQ + q0)) * DD + h * HDIM;
    const float inv0 = 1.f / l_i[0];
    const float inv1 = 1.f / l_i[1];
    #pragma unroll
    for (int nf = 0; nf < 8; nf++) {
        const int col = nf * 8 + tg * 2;
        const int r0 = wrow + g;
        *reinterpret_cast<__nv_bfloat162*>(Ob + (size_t)r0 * DD + col) =
            __floats2bfloat162_rn(of[nf][0] * inv0, of[nf][1] * inv0);
        *reinterpret_cast<__nv_bfloat162*>(Ob + (size_t)(r0 + 8) * DD + col) =
            __floats2bfloat162_rn(of[nf][2] * inv1, of[nf][3] * inv1);
    }
}

// ---------------------------------------------------------------------------
// Launcher
// ---------------------------------------------------------------------------
extern "C" void kernel_launch(void* const* d_in, const int* in_sizes, int n_in,
                              void* d_out, int out_size)
{
    const float* query   = (const float*)d_in[0];
    const float* context = (const float*)d_in[1];
    const float* wq = (const float*)d_in[2];
    const float* bq = (const float*)d_in[3];
    const float* wk = (const float*)d_in[4];
    const float* bk = (const float*)d_in[5];
    const float* wv = (const float*)d_in[6];
    const float* bv = (const float*)d_in[7];
    const float* wo = (const float*)d_in[8];
    const float* bo = (const float*)d_in[9];
    const float* g_q  = (const float*)d_in[10];
    const float* b_q  = (const float*)d_in[11];
    const float* g_kv = (const float*)d_in[12];
    const float* b_kv = (const float*)d_in[13];
    float* out = (float*)d_out;

    void *qn_, *qnh_, *cnh_, *qp_, *kp_, *vp_, *ao_, *wqh_, *wkvh_, *woh_;
    cudaGetSymbolAddress(&qn_,   g_qn);
    cudaGetSymbolAddress(&qnh_,  g_qnh);
    cudaGetSymbolAddress(&cnh_,  g_cnh);
    cudaGetSymbolAddress(&qp_,   g_Qp);
    cudaGetSymbolAddress(&kp_,   g_Kp);
    cudaGetSymbolAddress(&vp_,   g_Vp);
    cudaGetSymbolAddress(&ao_,   g_AO);
    cudaGetSymbolAddress(&wqh_,  g_wqh);
    cudaGetSymbolAddress(&wkvh_, g_wkvh);
    cudaGetSymbolAddress(&woh_,  g_woh);
    float* qn = (float*)qn_;
    __nv_bfloat16* qnh  = (__nv_bfloat16*)qnh_;
    __nv_bfloat16* cnh  = (__nv_bfloat16*)cnh_;
    __nv_bfloat16* Qp   = (__nv_bfloat16*)qp_;
    __nv_bfloat16* Kp   = (__nv_bfloat16*)kp_;
    __nv_bfloat16* Vp   = (__nv_bfloat16*)vp_;
    __nv_bfloat16* AO   = (__nv_bfloat16*)ao_;
    __nv_bfloat16* wqh  = (__nv_bfloat16*)wqh_;
    __nv_bfloat16* wkvh = (__nv_bfloat16*)wkvh_;
    __nv_bfloat16* woh  = (__nv_bfloat16*)woh_;

    const int attn_smem = SM_ELEMS * 2;      // 55296 bytes
    static int configured = 0;
    if (!configured) {
        cudaFuncSetAttribute(attn_bf16_kernel,
                             cudaFuncAttributeMaxDynamicSharedMemorySize, attn_smem);
        cudaFuncSetAttribute(proj_fused_kernel,
                             cudaFuncAttributeMaxDynamicSharedMemorySize, GEMM_SMEM);
        cudaFuncSetAttribute(oproj_kernel,
                             cudaFuncAttributeMaxDynamicSharedMemorySize, GEMM_SMEM);
        configured = 1;
    }

    // 0. Weight conversion fp32 -> bf16
    dim3 gcvt((DD * DD / 4) / 256, 4);
    cvt4_kernel<<<gcvt, 256>>>(wq, wk, wv, wo, wqh, wkvh, woh);

    // 1. Fused LayerNorms
    ln_fused_kernel<<<MQ + MC, 256>>>(query, context, g_q, b_q, g_kv, b_kv,
                                      qn, qnh, cnh);

    // 2. Fused Q + KV projections
    proj_fused_kernel<<<1152, 256, GEMM_SMEM>>>(qnh, cnh, wqh, wkvh,
                                                bq, bk, bv, Qp, Kp, Vp);

    // 3. Flash attention (P in registers)
    dim3 ga(NQ / 128, NH, BB);          // (8, 16, 2)
    attn_bf16_kernel<<<ga, 256, attn_smem>>>(Qp, Kp, Vp, AO);

    // 4. Output projection + bias + residual(qn), fp32 out
    dim3 go(DD / 128, MQ / 128);        // (8, 16)
    oproj_kernel<<<go, 256, GEMM_SMEM>>>(AO, woh, bo, qn, out);
}

// round 8
// speedup vs baseline: 7.2858x; 1.0313x over previous
#include <cuda_runtime.h>
#include <cuda_bf16.h>
#include <math.h>

// Problem constants
#define DD   1024
#define NH   16
#define HDIM 64
#define BB   2
#define NQ   1024
#define NC   4096
#define MQ   (BB*NQ)   // 2048 query rows
#define MC   (BB*NC)   // 8192 context rows

// Scratch (static device globals: allocation-free)
__device__ float         g_qn  [(size_t)MQ*DD];   // fp32 qn (residual)
__device__ __nv_bfloat16 g_qnh [(size_t)MQ*DD];
__device__ __nv_bfloat16 g_cnh [(size_t)MC*DD];
__device__ __nv_bfloat16 g_Qp  [(size_t)MQ*DD];
__device__ __nv_bfloat16 g_Kp  [(size_t)MC*DD];
__device__ __nv_bfloat16 g_Vp  [(size_t)MC*DD];
__device__ __nv_bfloat16 g_AO  [(size_t)MQ*DD];
__device__ __nv_bfloat16 g_wqh [(size_t)DD*DD];
__device__ __nv_bfloat16 g_wkvh[(size_t)2*DD*DD]; // concat [wk; wv]
__device__ __nv_bfloat16 g_woh [(size_t)DD*DD];

// ---------------------------------------------------------------------------
// PTX helpers
// ---------------------------------------------------------------------------
__device__ __forceinline__ void mma_bf16(float* c, const unsigned* a,
                                         unsigned b0, unsigned b1) {
    asm volatile(
        "mma.sync.aligned.m16n8k16.row.col.f32.bf16.bf16.f32 "
        "{%0,%1,%2,%3}, {%4,%5,%6,%7}, {%8,%9}, {%0,%1,%2,%3};"
        : "+f"(c[0]), "+f"(c[1]), "+f"(c[2]), "+f"(c[3])
        : "r"(a[0]), "r"(a[1]), "r"(a[2]), "r"(a[3]), "r"(b0), "r"(b1));
}

__device__ __forceinline__ void ldsm_x4(unsigned& r0, unsigned& r1,
                                        unsigned& r2, unsigned& r3, unsigned addr) {
    asm volatile("ldmatrix.sync.aligned.m8n8.x4.shared.b16 {%0,%1,%2,%3}, [%4];"
                 : "=r"(r0), "=r"(r1), "=r"(r2), "=r"(r3) : "r"(addr));
}

__device__ __forceinline__ void ldsm_x4_trans(unsigned& r0, unsigned& r1,
                                              unsigned& r2, unsigned& r3, unsigned addr) {
    asm volatile("ldmatrix.sync.aligned.m8n8.x4.trans.shared.b16 {%0,%1,%2,%3}, [%4];"
                 : "=r"(r0), "=r"(r1), "=r"(r2), "=r"(r3) : "r"(addr));
}

__device__ __forceinline__ void cp_async16(unsigned dst, const void* src) {
    asm volatile("cp.async.cg.shared.global [%0], [%1], 16;" :: "r"(dst), "l"(src));
}
__device__ __forceinline__ void cp_commit() {
    asm volatile("cp.async.commit_group;");
}
template <int N>
__device__ __forceinline__ void cp_wait() {
    asm volatile("cp.async.wait_group %0;" :: "n"(N));
}

// pack two fp32 into bf16x2 register (lo, hi)
__device__ __forceinline__ unsigned pack_bf16x2(float lo, float hi) {
    __nv_bfloat162 h = __floats2bfloat162_rn(lo, hi);
    return *reinterpret_cast<unsigned*>(&h);
}

// ---------------------------------------------------------------------------
// Fused weight convert fp32 -> bf16
// ---------------------------------------------------------------------------
__global__ void __launch_bounds__(256) cvt4_kernel(
    const float* __restrict__ wq, const float* __restrict__ wk,
    const float* __restrict__ wv, const float* __restrict__ wo,
    __nv_bfloat16* __restrict__ wqh, __nv_bfloat16* __restrict__ wkvh,
    __nv_bfloat16* __restrict__ woh)
{
    const int i = (blockIdx.x * 256 + threadIdx.x) * 4;
    const int m = blockIdx.y;
    const float* s;
    __nv_bfloat16* d;
    if      (m == 0) { s = wq; d = wqh; }
    else if (m == 1) { s = wk; d = wkvh; }
    else if (m == 2) { s = wv; d = wkvh + (size_t)DD * DD; }
    else             { s = wo; d = woh; }
    const float4 v = *reinterpret_cast<const float4*>(s + i);
    __nv_bfloat162* o = reinterpret_cast<__nv_bfloat162*>(d + i);
    o[0] = __floats2bfloat162_rn(v.x, v.y);
    o[1] = __floats2bfloat162_rn(v.z, v.w);
}

// ---------------------------------------------------------------------------
// Fused LayerNorm
// ---------------------------------------------------------------------------
__global__ void __launch_bounds__(256) ln_fused_kernel(
    const float* __restrict__ query, const float* __restrict__ context,
    const float* __restrict__ gq, const float* __restrict__ bq,
    const float* __restrict__ gkv, const float* __restrict__ bkv,
    float* __restrict__ qn, __nv_bfloat16* __restrict__ qnh,
    __nv_bfloat16* __restrict__ cnh)
{
    const int bid = blockIdx.x;
    const bool isq = (bid < MQ);
    const int row = isq ? bid : bid - MQ;
    const float* x = isq ? (query + (size_t)row * DD) : (context + (size_t)row * DD);
    const float* gamma = isq ? gq : gkv;
    const float* beta  = isq ? bq : bkv;
    __nv_bfloat16* yh = isq ? (qnh + (size_t)row * DD) : (cnh + (size_t)row * DD);

    int t = threadIdx.x;
    const float4 v = reinterpret_cast<const float4*>(x)[t];
    float s  = v.x + v.y + v.z + v.w;
    float ss = v.x*v.x + v.y*v.y + v.z*v.z + v.w*v.w;
    #pragma unroll
    for (int o = 16; o > 0; o >>= 1) {
        s  += __shfl_xor_sync(0xffffffffu, s,  o);
        ss += __shfl_xor_sync(0xffffffffu, ss, o);
    }
    __shared__ float sm1[8], sm2[8];
    int w = t >> 5, l = t & 31;
    if (l == 0) { sm1[w] = s; sm2[w] = ss; }
    __syncthreads();
    if (t < 32) {
        s  = (l < 8) ? sm1[l] : 0.f;
        ss = (l < 8) ? sm2[l] : 0.f;
        #pragma unroll
        for (int o = 4; o > 0; o >>= 1) {
            s  += __shfl_xor_sync(0xffffffffu, s,  o);
            ss += __shfl_xor_sync(0xffffffffu, ss, o);
        }
        if (l == 0) { sm1[0] = s; sm2[0] = ss; }
    }
    __syncthreads();
    const float mu  = sm1[0] * (1.f / DD);
    const float var = sm2[0] * (1.f / DD) - mu * mu;
    const float inv = rsqrtf(var + 1e-5f);
    const float4 g = reinterpret_cast<const float4*>(gamma)[t];
    const float4 b = reinterpret_cast<const float4*>(beta)[t];
    float4 o;
    o.x = (v.x - mu) * inv * g.x + b.x;
    o.y = (v.y - mu) * inv * g.y + b.y;
    o.z = (v.z - mu) * inv * g.z + b.z;
    o.w = (v.w - mu) * inv * g.w + b.w;
    if (isq) reinterpret_cast<float4*>(qn + (size_t)row * DD)[t] = o;
    __nv_bfloat162* oh = reinterpret_cast<__nv_bfloat162*>(yh + t * 4);
    oh[0] = __floats2bfloat162_rn(o.x, o.y);
    oh[1] = __floats2bfloat162_rn(o.z, o.w);
}

// ---------------------------------------------------------------------------
// GEMM mainloop core: 128x128x32 tile, 4-stage cp.async pipeline,
// 256 threads = 8 warps (4m x 2n), warp tile 32x64, smem stride 40 bf16.
// ---------------------------------------------------------------------------
#define RS 40
#define GTILE (128 * RS)
#define GSTAGES 4
#define GEMM_SMEM (2 * GSTAGES * GTILE * 2)

struct GemmCtx {
    const __nv_bfloat16 *A, *W;
    int m0, n0;
};

__device__ __forceinline__ void gemm_mainloop(
    const GemmCtx& cx, __nv_bfloat16* gsm, float acc[2][8][4])
{
    __nv_bfloat16* As = gsm;
    __nv_bfloat16* Bs = gsm + GSTAGES * GTILE;
    const int t    = threadIdx.x;
    const int lane = t & 31;
    const int w    = t >> 5;
    const int wm   = w >> 1;
    const int wn   = w & 1;

    const unsigned as_base = (unsigned)__cvta_generic_to_shared(As);
    const unsigned bs_base = (unsigned)__cvta_generic_to_shared(Bs);

    const int arow_in  = (lane & 7) + ((lane >> 3) & 1) * 8;
    const int akoff_in = (lane >> 4) * 8;
    const int brow_in  = (lane & 7) + (lane >> 4) * 8;
    const int bkoff_in = ((lane >> 3) & 1) * 8;

    const int srow = t >> 1;
    const int sc   = (t & 1) * 16;

    const __nv_bfloat16* Ap = cx.A + (size_t)(cx.m0 + srow) * DD + sc;
    const __nv_bfloat16* Wp = cx.W + (size_t)(cx.n0 + srow) * DD + sc;
    const unsigned a_dst = as_base + (srow * RS + sc) * 2;
    const unsigned b_dst = bs_base + (srow * RS + sc) * 2;

    const int NK = DD / 32;

    #pragma unroll
    for (int st = 0; st < GSTAGES - 1; st++) {
        cp_async16(a_dst + st * GTILE * 2,      Ap + st * 32);
        cp_async16(a_dst + st * GTILE * 2 + 16, Ap + st * 32 + 8);
        cp_async16(b_dst + st * GTILE * 2,      Wp + st * 32);
        cp_async16(b_dst + st * GTILE * 2 + 16, Wp + st * 32 + 8);
        cp_commit();
    }

    #pragma unroll
    for (int mf = 0; mf < 2; mf++)
        #pragma unroll
        for (int nf = 0; nf < 8; nf++)
            #pragma unroll
            for (int i = 0; i < 4; i++) acc[mf][nf][i] = 0.f;

    int cur = 0, nxt = GSTAGES - 1;
    for (int it = 0; it < NK; it++) {
        if (it + 2 < NK)      cp_wait<2>();
        else if (it + 1 < NK) cp_wait<1>();
        else                  cp_wait<0>();
        __syncthreads();

        if (it + GSTAGES - 1 < NK) {
            const int ko = (it + GSTAGES - 1) * 32;
            cp_async16(a_dst + nxt * GTILE * 2,      Ap + ko);
            cp_async16(a_dst + nxt * GTILE * 2 + 16, Ap + ko + 8);
            cp_async16(b_dst + nxt * GTILE * 2,      Wp + ko);
            cp_async16(b_dst + nxt * GTILE * 2 + 16, Wp + ko + 8);
            cp_commit();
        }

        const unsigned as_st = as_base + cur * GTILE * 2;
        const unsigned bs_st = bs_base + cur * GTILE * 2;

        #pragma unroll
        for (int ks = 0; ks < 2; ks++) {
            unsigned a[2][4];
            #pragma unroll
            for (int mf = 0; mf < 2; mf++) {
                const int r  = wm * 32 + mf * 16 + arow_in;
                const int ko = ks * 16 + akoff_in;
                ldsm_x4(a[mf][0], a[mf][1], a[mf][2], a[mf][3],
                        as_st + (r * RS + ko) * 2);
            }
            unsigned bf[4][4];
            #pragma unroll
            for (int ng = 0; ng < 4; ng++) {
                const int nr = wn * 64 + ng * 16 + brow_in;
                const int ko = ks * 16 + bkoff_in;
                ldsm_x4(bf[ng][0], bf[ng][1], bf[ng][2], bf[ng][3],
                        bs_st + (nr * RS + ko) * 2);
            }
            #pragma unroll
            for (int ng = 0; ng < 4; ng++) {
                mma_bf16(acc[0][2*ng+0], a[0], bf[ng][0], bf[ng][1]);
                mma_bf16(acc[1][2*ng+0], a[1], bf[ng][0], bf[ng][1]);
                mma_bf16(acc[0][2*ng+1], a[0], bf[ng][2], bf[ng][3]);
                mma_bf16(acc[1][2*ng+1], a[1], bf[ng][2], bf[ng][3]);
            }
        }

        cur = (cur + 1) & (GSTAGES - 1);
        nxt = (nxt + 1) & (GSTAGES - 1);
    }
}

// ---------------------------------------------------------------------------
// Fused Q + KV projection: grid = 1024 KV CTAs then 128 Q CTAs.
// ---------------------------------------------------------------------------
__global__ void __launch_bounds__(256) proj_fused_kernel(
    const __nv_bfloat16* __restrict__ qnh, const __nv_bfloat16* __restrict__ cnh,
    const __nv_bfloat16* __restrict__ wqh, const __nv_bfloat16* __restrict__ wkvh,
    const float* __restrict__ bq, const float* __restrict__ bk,
    const float* __restrict__ bv,
    __nv_bfloat16* __restrict__ Qp, __nv_bfloat16* __restrict__ Kp,
    __nv_bfloat16* __restrict__ Vp)
{
    extern __shared__ __align__(16) __nv_bfloat16 gsm[];

    GemmCtx cx;
    const float* bias;
    __nv_bfloat16* Co;
    int nbase;
    const int bid = blockIdx.x;
    if (bid < 1024) {
        cx.A = cnh; cx.W = wkvh;
        cx.m0 = (bid >> 4) * 128;
        cx.n0 = (bid & 15) * 128;
        if (cx.n0 < DD) { bias = bk; Co = Kp; nbase = cx.n0; }
        else            { bias = bv; Co = Vp; nbase = cx.n0 - DD; }
    } else {
        const int i2 = bid - 1024;
        cx.A = qnh; cx.W = wqh;
        cx.m0 = (i2 >> 3) * 128;
        cx.n0 = (i2 & 7) * 128;
        bias = bq; Co = Qp; nbase = cx.n0;
    }

    float acc[2][8][4];
    gemm_mainloop(cx, gsm, acc);

    const int t = threadIdx.x, lane = t & 31, w = t >> 5;
    const int wm = w >> 1, wn = w & 1, g = lane >> 2, tg = lane & 3;

    #pragma unroll
    for (int mf = 0; mf < 2; mf++) {
        #pragma unroll
        for (int nf = 0; nf < 8; nf++) {
            const int col = nbase + wn * 64 + nf * 8 + tg * 2;
            const float bx = bias[col], by = bias[col + 1];
            #pragma unroll
            for (int half = 0; half < 2; half++) {
                const size_t grow = (size_t)(cx.m0 + wm * 32 + mf * 16 + g + half * 8);
                *reinterpret_cast<__nv_bfloat162*>(Co + grow * DD + col) =
                    __floats2bfloat162_rn(acc[mf][nf][half * 2 + 0] + bx,
                                          acc[mf][nf][half * 2 + 1] + by);
            }
        }
    }
}

// ---------------------------------------------------------------------------
// O projection + bias + residual (fp32 out)
// ---------------------------------------------------------------------------
__global__ void __launch_bounds__(256) oproj_kernel(
    const __nv_bfloat16* __restrict__ A, const __nv_bfloat16* __restrict__ W,
    const float* __restrict__ bias, const float* __restrict__ R,
    float* __restrict__ Cf)
{
    extern __shared__ __align__(16) __nv_bfloat16 gsm[];

    GemmCtx cx;
    cx.A = A; cx.W = W;
    cx.m0 = blockIdx.y * 128;
    cx.n0 = blockIdx.x * 128;

    float acc[2][8][4];
    gemm_mainloop(cx, gsm, acc);

    const int t = threadIdx.x, lane = t & 31, w = t >> 5;
    const int wm = w >> 1, wn = w & 1, g = lane >> 2, tg = lane & 3;

    #pragma unroll
    for (int mf = 0; mf < 2; mf++) {
        #pragma unroll
        for (int nf = 0; nf < 8; nf++) {
            const int col = cx.n0 + wn * 64 + nf * 8 + tg * 2;
            const float bx = bias[col], by = bias[col + 1];
            #pragma unroll
            for (int half = 0; half < 2; half++) {
                const size_t grow = (size_t)(cx.m0 + wm * 32 + mf * 16 + g + half * 8);
                const float2 rv = *reinterpret_cast<const float2*>(R + grow * DD + col);
                float2 o;
                o.x = acc[mf][nf][half * 2 + 0] + bx + rv.x;
                o.y = acc[mf][nf][half * 2 + 1] + by + rv.y;
                *reinterpret_cast<float2*>(Cf + grow * DD + col) = o;
            }
        }
    }
}

// ---------------------------------------------------------------------------
// BF16 flash attention: 128 threads = 4 warps, q-tile 128, warp tile m32xn64.
// K/V fragments loaded once per ks and shared across both m-halves
// (1 L1 wavefront per MMA instead of 2). Q fragments hoisted out of the
// KV loop. P in registers. exp2-domain softmax, raw-unit m_i.
// ---------------------------------------------------------------------------
#define QSTR 72
#define OFF_Q 0
#define OFF_K (128 * QSTR)
#define OFF_V (OFF_K + 2 * 64 * QSTR)
#define SM_ELEMS (OFF_V + 2 * 64 * QSTR)
#define KVBUF (64 * QSTR)
#define SSCALE 0.18033688f   /* 0.125 * log2(e) */

__global__ void __launch_bounds__(128) attn_bf16_kernel(
    const __nv_bfloat16* __restrict__ Q, const __nv_bfloat16* __restrict__ K,
    const __nv_bfloat16* __restrict__ V, __nv_bfloat16* __restrict__ O)
{
    extern __shared__ __align__(16) __nv_bfloat16 smem[];
    const unsigned sm_base = (unsigned)__cvta_generic_to_shared(smem);

    const int b  = blockIdx.z;
    const int h  = blockIdx.y;
    const int q0 = blockIdx.x * 128;
    const int t  = threadIdx.x;
    const int w  = t >> 5;           // 0..3
    const int lane = t & 31;
    const int g  = lane >> 2;
    const int tg = lane & 3;
    const int wrow = w * 32;         // warp's 32 q rows

    const int arow_in  = (lane & 7) + ((lane >> 3) & 1) * 8;
    const int akoff_in = (lane >> 4) * 8;
    const int brow_in  = (lane & 7) + (lane >> 4) * 8;
    const int bkoff_in = ((lane >> 3) & 1) * 8;

    const __nv_bfloat16* Qb = Q + ((size_t)(b * NQ + q0)) * DD + h * HDIM;
    const __nv_bfloat16* Kb = K + ((size_t)(b * NC)) * DD + h * HDIM;
    const __nv_bfloat16* Vb = V + ((size_t)(b * NC)) * DD + h * HDIM;

    // Prologue: Q (group 0), then K/V tile 0 (group 1)
    #pragma unroll
    for (int i = t; i < 128 * 8; i += 128) {
        const int r = i >> 3, c = (i & 7) * 8;
        cp_async16(sm_base + (OFF_Q + r * QSTR + c) * 2, Qb + (size_t)r * DD + c);
    }
    cp_commit();
    #pragma unroll
    for (int i = t; i < 64 * 8; i += 128) {
        const int r = i >> 3, c = (i & 7) * 8;
        cp_async16(sm_base + (OFF_K + r * QSTR + c) * 2, Kb + (size_t)r * DD + c);
        cp_async16(sm_base + (OFF_V + r * QSTR + c) * 2, Vb + (size_t)r * DD + c);
    }
    cp_commit();

    // Q ready (<=1 group pending); hoist Q fragments into registers
    cp_wait<1>();
    __syncthreads();
    unsigned qa[2][4][4];
    #pragma unroll
    for (int mf = 0; mf < 2; mf++)
        #pragma unroll
        for (int ks = 0; ks < 4; ks++)
            ldsm_x4(qa[mf][ks][0], qa[mf][ks][1], qa[mf][ks][2], qa[mf][ks][3],
                    sm_base + (OFF_Q + (wrow + mf * 16 + arow_in) * QSTR
                               + ks * 16 + akoff_in) * 2);

    float m_i[4], l_i[4], of[2][8][4];
    #pragma unroll
    for (int i = 0; i < 4; i++) { m_i[i] = -INFINITY; l_i[i] = 0.f; }
    #pragma unroll
    for (int mf = 0; mf < 2; mf++)
        #pragma unroll
        for (int nf = 0; nf < 8; nf++)
            #pragma unroll
            for (int i = 0; i < 4; i++) of[mf][nf][i] = 0.f;

    const int NT = NC / 64;
    for (int it = 0; it < NT; it++) {
        const int cur = it & 1;
        cp_wait<0>();
        __syncthreads();

        if (it + 1 < NT) {
            const int nxt = cur ^ 1;
            #pragma unroll
            for (int i = t; i < 64 * 8; i += 128) {
                const int r = i >> 3, c = (i & 7) * 8;
                const size_t grow = (size_t)((it + 1) * 64 + r) * DD + c;
                cp_async16(sm_base + (OFF_K + nxt * KVBUF + r * QSTR + c) * 2, Kb + grow);
                cp_async16(sm_base + (OFF_V + nxt * KVBUF + r * QSTR + c) * 2, Vb + grow);
            }
            cp_commit();
        }

        const int kbase = OFF_K + cur * KVBUF;
        const int vbase = OFF_V + cur * KVBUF;

        // ---- S = Q K^T : warp m32 x n64 over k=64; K frags shared by m-halves
        float sf[2][8][4];
        #pragma unroll
        for (int mf = 0; mf < 2; mf++)
            #pragma unroll
            for (int nf = 0; nf < 8; nf++)
                #pragma unroll
                for (int i = 0; i < 4; i++) sf[mf][nf][i] = 0.f;

        #pragma unroll
        for (int ks = 0; ks < 4; ks++) {
            unsigned bf[4][4];
            #pragma unroll
            for (int ng = 0; ng < 4; ng++) {
                ldsm_x4(bf[ng][0], bf[ng][1], bf[ng][2], bf[ng][3],
                        sm_base + (kbase + (ng * 16 + brow_in) * QSTR
                                   + ks * 16 + bkoff_in) * 2);
            }
            #pragma unroll
            for (int ng = 0; ng < 4; ng++) {
                mma_bf16(sf[0][2*ng+0], qa[0][ks], bf[ng][0], bf[ng][1]);
                mma_bf16(sf[1][2*ng+0], qa[1][ks], bf[ng][0], bf[ng][1]);
                mma_bf16(sf[0][2*ng+1], qa[0][ks], bf[ng][2], bf[ng][3]);
                mma_bf16(sf[1][2*ng+1], qa[1][ks], bf[ng][2], bf[ng][3]);
            }
        }

        // ---- online softmax per m-half; P packed into A-fragments ----
        unsigned pa[2][4][4];
        #pragma unroll
        for (int mf = 0; mf < 2; mf++) {
            float mx0 = -INFINITY, mx1 = -INFINITY;
            #pragma unroll
            for (int nf = 0; nf < 8; nf++) {
                mx0 = fmaxf(mx0, fmaxf(sf[mf][nf][0], sf[mf][nf][1]));
                mx1 = fmaxf(mx1, fmaxf(sf[mf][nf][2], sf[mf][nf][3]));
            }
            mx0 = fmaxf(mx0, __shfl_xor_sync(0xffffffffu, mx0, 1));
            mx0 = fmaxf(mx0, __shfl_xor_sync(0xffffffffu, mx0, 2));
            mx1 = fmaxf(mx1, __shfl_xor_sync(0xffffffffu, mx1, 1));
            mx1 = fmaxf(mx1, __shfl_xor_sync(0xffffffffu, mx1, 2));

            const float mn0 = fmaxf(m_i[mf * 2 + 0], mx0);   // raw units
            const float mn1 = fmaxf(m_i[mf * 2 + 1], mx1);
            const float f0 = exp2f((m_i[mf * 2 + 0] - mn0) * SSCALE);
            const float f1 = exp2f((m_i[mf * 2 + 1] - mn1) * SSCALE);
            const float c0 = mn0 * SSCALE;
            const float c1 = mn1 * SSCALE;

            float s0 = 0.f, s1 = 0.f;
            #pragma unroll
            for (int nf = 0; nf < 8; nf++) {
                const float p0 = exp2f(fmaf(sf[mf][nf][0], SSCALE, -c0));
                const float p1 = exp2f(fmaf(sf[mf][nf][1], SSCALE, -c0));
                const float p2 = exp2f(fmaf(sf[mf][nf][2], SSCALE, -c1));
                const float p3 = exp2f(fmaf(sf[mf][nf][3], SSCALE, -c1));
                s0 += p0 + p1;
                s1 += p2 + p3;
                const int ks = nf >> 1, hf = nf & 1;
                pa[mf][ks][hf * 2 + 0] = pack_bf16x2(p0, p1);   // row g
                pa[mf][ks][hf * 2 + 1] = pack_bf16x2(p2, p3);   // row g+8
            }
            s0 += __shfl_xor_sync(0xffffffffu, s0, 1);
            s0 += __shfl_xor_sync(0xffffffffu, s0, 2);
            s1 += __shfl_xor_sync(0xffffffffu, s1, 1);
            s1 += __shfl_xor_sync(0xffffffffu, s1, 2);

            l_i[mf * 2 + 0] = l_i[mf * 2 + 0] * f0 + s0;
            l_i[mf * 2 + 1] = l_i[mf * 2 + 1] * f1 + s1;
            m_i[mf * 2 + 0] = mn0;
            m_i[mf * 2 + 1] = mn1;

            #pragma unroll
            for (int nf = 0; nf < 8; nf++) {
                of[mf][nf][0] *= f0; of[mf][nf][1] *= f0;
                of[mf][nf][2] *= f1; of[mf][nf][3] *= f1;
            }
        }

        // ---- O += P V : V frags shared by both m-halves ----
        #pragma unroll
        for (int ks = 0; ks < 4; ks++) {
            unsigned bf[4][4];
            #pragma unroll
            for (int ng = 0; ng < 4; ng++) {
                ldsm_x4_trans(bf[ng][0], bf[ng][1], bf[ng][2], bf[ng][3],
                              sm_base + (vbase + (ks * 16 + arow_in) * QSTR
                                         + ng * 16 + akoff_in) * 2);
            }
            #pragma unroll
            for (int ng = 0; ng < 4; ng++) {
                mma_bf16(of[0][2*ng+0], pa[0][ks], bf[ng][0], bf[ng][1]);
                mma_bf16(of[1][2*ng+0], pa[1][ks], bf[ng][0], bf[ng][1]);
                mma_bf16(of[0][2*ng+1], pa[0][ks], bf[ng][2], bf[ng][3]);
                mma_bf16(of[1][2*ng+1], pa[1][ks], bf[ng][2], bf[ng][3]);
            }
        }
    }

    // Epilogue
    __nv_bfloat16* Ob = O + ((size_t)(b * NQ + q0)) * DD + h * HDIM;
    #pragma unroll
    for (int mf = 0; mf < 2; mf++) {
        const float inv0 = 1.f / l_i[mf * 2 + 0];
        const float inv1 = 1.f / l_i[mf * 2 + 1];
        #pragma unroll
        for (int nf = 0; nf < 8; nf++) {
            const int col = nf * 8 + tg * 2;
            const int r0 = wrow + mf * 16 + g;
            *reinterpret_cast<__nv_bfloat162*>(Ob + (size_t)r0 * DD + col) =
                __floats2bfloat162_rn(of[mf][nf][0] * inv0, of[mf][nf][1] * inv0);
            *reinterpret_cast<__nv_bfloat162*>(Ob + (size_t)(r0 + 8) * DD + col) =
                __floats2bfloat162_rn(of[mf][nf][2] * inv1, of[mf][nf][3] * inv1);
        }
    }
}

// ---------------------------------------------------------------------------
// Launcher
// ---------------------------------------------------------------------------
extern "C" void kernel_launch(void* const* d_in, const int* in_sizes, int n_in,
                              void* d_out, int out_size)
{
    const float* query   = (const float*)d_in[0];
    const float* context = (const float*)d_in[1];
    const float* wq = (const float*)d_in[2];
    const float* bq = (const float*)d_in[3];
    const float* wk = (const float*)d_in[4];
    const float* bk = (const float*)d_in[5];
    const float* wv = (const float*)d_in[6];
    const float* bv = (const float*)d_in[7];
    const float* wo = (const float*)d_in[8];
    const float* bo = (const float*)d_in[9];
    const float* g_q  = (const float*)d_in[10];
    const float* b_q  = (const float*)d_in[11];
    const float* g_kv = (const float*)d_in[12];
    const float* b_kv = (const float*)d_in[13];
    float* out = (float*)d_out;

    void *qn_, *qnh_, *cnh_, *qp_, *kp_, *vp_, *ao_, *wqh_, *wkvh_, *woh_;
    cudaGetSymbolAddress(&qn_,   g_qn);
    cudaGetSymbolAddress(&qnh_,  g_qnh);
    cudaGetSymbolAddress(&cnh_,  g_cnh);
    cudaGetSymbolAddress(&qp_,   g_Qp);
    cudaGetSymbolAddress(&kp_,   g_Kp);
    cudaGetSymbolAddress(&vp_,   g_Vp);
    cudaGetSymbolAddress(&ao_,   g_AO);
    cudaGetSymbolAddress(&wqh_,  g_wqh);
    cudaGetSymbolAddress(&wkvh_, g_wkvh);
    cudaGetSymbolAddress(&woh_,  g_woh);
    float* qn = (float*)qn_;
    __nv_bfloat16* qnh  = (__nv_bfloat16*)qnh_;
    __nv_bfloat16* cnh  = (__nv_bfloat16*)cnh_;
    __nv_bfloat16* Qp   = (__nv_bfloat16*)qp_;
    __nv_bfloat16* Kp   = (__nv_bfloat16*)kp_;
    __nv_bfloat16* Vp   = (__nv_bfloat16*)vp_;
    __nv_bfloat16* AO   = (__nv_bfloat16*)ao_;
    __nv_bfloat16* wqh  = (__nv_bfloat16*)wqh_;
    __nv_bfloat16* wkvh = (__nv_bfloat16*)wkvh_;
    __nv_bfloat16* woh  = (__nv_bfloat16*)woh_;

    const int attn_smem = SM_ELEMS * 2;      // 55296 bytes
    static int configured = 0;
    if (!configured) {
        cudaFuncSetAttribute(attn_bf16_kernel,
                             cudaFuncAttributeMaxDynamicSharedMemorySize, attn_smem);
        cudaFuncSetAttribute(proj_fused_kernel,
                             cudaFuncAttributeMaxDynamicSharedMemorySize, GEMM_SMEM);
        cudaFuncSetAttribute(oproj_kernel,
                             cudaFuncAttributeMaxDynamicSharedMemorySize, GEMM_SMEM);
        configured = 1;
    }

    // 0. Weight conversion fp32 -> bf16
    dim3 gcvt((DD * DD / 4) / 256, 4);
    cvt4_kernel<<<gcvt, 256>>>(wq, wk, wv, wo, wqh, wkvh, woh);

    // 1. Fused LayerNorms
    ln_fused_kernel<<<MQ + MC, 256>>>(query, context, g_q, b_q, g_kv, b_kv,
                                      qn, qnh, cnh);

    // 2. Fused Q + KV projections
    proj_fused_kernel<<<1152, 256, GEMM_SMEM>>>(qnh, cnh, wqh, wkvh,
                                                bq, bk, bv, Qp, Kp, Vp);

    // 3. Flash attention (4 warps, m32 warp tile, shared K/V frags)
    dim3 ga(NQ / 128, NH, BB);          // (8, 16, 2)
    attn_bf16_kernel<<<ga, 128, attn_smem>>>(Qp, Kp, Vp, AO);

    // 4. Output projection + bias + residual(qn), fp32 out
    dim3 go(DD / 128, MQ / 128);        // (8, 16)
    oproj_kernel<<<go, 256, GEMM_SMEM>>>(AO, woh, bo, qn, out);
}